// round 11
// baseline (speedup 1.0000x reference)
#include <cuda_runtime.h>
#include <cuda_bf16.h>
#include <math_constants.h>
#include <cstdint>

// ---------------- problem constants ----------------
#define B_    2
#define S_    2048
#define DIM_  2048
#define NH_   16
#define DQK_  192
#define DNOPE_ 128
#define DROPE_ 64
#define DV_   128
#define RANK_ 512
#define M_    (B_*S_)          // 4096
#define NQ_   (NH_*DQK_)       // 3072
#define NKV_  (RANK_+DROPE_)   // 576
#define NUP_  (NH_*(DNOPE_+DV_)) // 4096
#define NO_   (NH_*DV_)        // 2048

// ---------------- scratch (device globals; no allocs allowed) ----------------
__device__ __nv_bfloat16 g_xh [M_*DIM_],  g_xl [M_*DIM_];
__device__ __nv_bfloat16 g_wqh[NQ_*DIM_], g_wql[NQ_*DIM_];
__device__ __nv_bfloat16 g_wah[NKV_*DIM_],g_wal[NKV_*DIM_];
__device__ __nv_bfloat16 g_wbh[NUP_*RANK_],g_wbl[NUP_*RANK_];
__device__ __nv_bfloat16 g_woh[DIM_*NO_], g_wol[DIM_*NO_];
__device__ __nv_bfloat16 g_kvnh[M_*RANK_],g_kvnl[M_*RANK_];
__device__ __nv_bfloat16 g_ath[M_*NO_],   g_atl[M_*NO_];
__device__ float g_q   [M_*NQ_];
__device__ float g_kv  [M_*NKV_];
__device__ float g_kpe [M_*DROPE_];
__device__ float g_kvup[M_*NUP_];
// head-major bf16 hi/lo operands for attention
__device__ __nv_bfloat16 g_qh[B_*NH_*S_*DQK_], g_ql[B_*NH_*S_*DQK_];
__device__ __nv_bfloat16 g_kh[B_*NH_*S_*DQK_], g_kl[B_*NH_*S_*DQK_];
__device__ __nv_bfloat16 g_vh[B_*NH_*S_*DV_],  g_vl[B_*NH_*S_*DV_];

// ---------------- PTX helpers ----------------
__device__ __forceinline__ uint32_t smem_u32(const void* p){
    uint32_t a;
    asm("{ .reg .u64 t; cvta.to.shared.u64 t, %1; cvt.u32.u64 %0, t; }"
        : "=r"(a) : "l"(p));
    return a;
}
__device__ __forceinline__ void cpa16(uint32_t dst, const void* src, int sz){
    asm volatile("cp.async.cg.shared.global [%0], [%1], 16, %2;"
                 :: "r"(dst), "l"(src), "r"(sz) : "memory");
}
#define CP_COMMIT() asm volatile("cp.async.commit_group;" ::: "memory")
#define CP_WAIT2()  asm volatile("cp.async.wait_group 2;" ::: "memory")
#define CP_WAIT0()  asm volatile("cp.async.wait_group 0;" ::: "memory")

__device__ __forceinline__ void ldsm4(uint32_t* r, uint32_t addr){
    asm volatile("ldmatrix.sync.aligned.m8n8.x4.shared.b16 {%0,%1,%2,%3}, [%4];"
        : "=r"(r[0]), "=r"(r[1]), "=r"(r[2]), "=r"(r[3]) : "r"(addr));
}
__device__ __forceinline__ void ldsm4t(uint32_t* r, uint32_t addr){
    asm volatile("ldmatrix.sync.aligned.m8n8.x4.trans.shared.b16 {%0,%1,%2,%3}, [%4];"
        : "=r"(r[0]), "=r"(r[1]), "=r"(r[2]), "=r"(r[3]) : "r"(addr));
}
__device__ __forceinline__ void mma16816(float* c, const uint32_t* a,
                                         uint32_t b0, uint32_t b1){
    asm volatile("mma.sync.aligned.m16n8k16.row.col.f32.bf16.bf16.f32 "
        "{%0,%1,%2,%3}, {%4,%5,%6,%7}, {%8,%9}, {%0,%1,%2,%3};"
        : "+f"(c[0]), "+f"(c[1]), "+f"(c[2]), "+f"(c[3])
        : "r"(a[0]), "r"(a[1]), "r"(a[2]), "r"(a[3]), "r"(b0), "r"(b1));
}
__device__ __forceinline__ float ex2f(float x){
    float y; asm("ex2.approx.ftz.f32 %0, %1;" : "=f"(y) : "f"(x)); return y;
}

// ---------------- hi/lo bf16 split ----------------
__device__ __forceinline__ void split_bf16(float v, __nv_bfloat16& h, __nv_bfloat16& l){
    h = __float2bfloat16(v);
    l = __float2bfloat16(v - __bfloat162float(h));
}
__device__ __forceinline__ void pksplit(float a, float b, uint32_t& hi, uint32_t& lo){
    __nv_bfloat16 ah, al, bh, bl;
    split_bf16(a, ah, al); split_bf16(b, bh, bl);
    __nv_bfloat162 H; H.x = ah; H.y = bh; hi = *(uint32_t*)&H;
    __nv_bfloat162 L; L.x = al; L.y = bl; lo = *(uint32_t*)&L;
}

__global__ void __launch_bounds__(256) k_cvt(const float* __restrict__ s,
                                             __nv_bfloat16* __restrict__ h,
                                             __nv_bfloat16* __restrict__ l, int n)
{
    int i = (blockIdx.x * 256 + threadIdx.x) * 4;
    if (i >= n) return;
    float4 v = *(const float4*)(s + i);
    __nv_bfloat16 h0, l0, h1, l1, h2, l2, h3, l3;
    split_bf16(v.x, h0, l0); split_bf16(v.y, h1, l1);
    split_bf16(v.z, h2, l2); split_bf16(v.w, h3, l3);
    __nv_bfloat162 p;
    p.x = h0; p.y = h1; *(__nv_bfloat162*)(h + i)     = p;
    p.x = h2; p.y = h3; *(__nv_bfloat162*)(h + i + 2) = p;
    p.x = l0; p.y = l1; *(__nv_bfloat162*)(l + i)     = p;
    p.x = l2; p.y = l3; *(__nv_bfloat162*)(l + i + 2) = p;
}

// ---------------- mma.sync GEMM (R6 proven config) ------------------
#define STG_BYTES 32768
#define GEMM_SMEM (3*STG_BYTES)

__device__ __forceinline__ void stage_load(uint32_t sdst,
    const char* ah, const char* al, const char* bh, const char* bl,
    int K2, int k0b, int nrem)
{
    const int tid = threadIdx.x;
#pragma unroll
    for (int p = 0; p < 2; p++){
        int idx = tid + p*256;
        int r = idx >> 2, c = idx & 3;
        uint32_t soff = (uint32_t)(r*64 + ((c ^ (r & 3)) << 4));
        size_t go = (size_t)r * K2 + k0b + c*16;
        cpa16(sdst + soff,        ah + go, 16);
        cpa16(sdst + 8192 + soff, al + go, 16);
        int rb = (r < nrem) ? r : 0;
        int sz = (r < nrem) ? 16 : 0;
        size_t gob = (size_t)rb * K2 + k0b + c*16;
        cpa16(sdst + 16384 + soff, bh + gob, sz);
        cpa16(sdst + 24576 + soff, bl + gob, sz);
    }
}

__global__ void __launch_bounds__(256, 2)
k_mmagemm(const __nv_bfloat16* __restrict__ Ah, const __nv_bfloat16* __restrict__ Al,
          const __nv_bfloat16* __restrict__ Bh, const __nv_bfloat16* __restrict__ Bl,
          float* __restrict__ C, int M, int N, int K)
{
    extern __shared__ char smc[];
    const int tid = threadIdx.x, wid = tid >> 5, lane = tid & 31;
    const int m0 = blockIdx.y * 128, n0 = blockIdx.x * 128;
    const int wm = (wid & 3) * 32, wn = (wid >> 2) * 64;
    const int nrem = N - n0;
    const int K2 = K * 2;
    const int nk = K / 32;

    uint32_t sbase = smem_u32(smc);
    const char* gAh = (const char*)(Ah + (size_t)m0 * K);
    const char* gAl = (const char*)(Al + (size_t)m0 * K);
    const char* gBh = (const char*)(Bh + (size_t)n0 * K);
    const char* gBl = (const char*)(Bl + (size_t)n0 * K);

#pragma unroll
    for (int s = 0; s < 2; s++){
        stage_load(sbase + s*STG_BYTES, gAh, gAl, gBh, gBl, K2, s*64, nrem);
        CP_COMMIT();
    }

    float acc[2][8][4];
#pragma unroll
    for (int a = 0; a < 2; a++)
#pragma unroll
        for (int b = 0; b < 8; b++)
#pragma unroll
            for (int c = 0; c < 4; c++) acc[a][b][c] = 0.f;

    int sidx = 0;
    for (int kt = 0; kt < nk; kt++){
        int ns = kt + 2;
        if (ns < nk){
            int fs = ns - 3*(ns/3);
            stage_load(sbase + fs*STG_BYTES, gAh, gAl, gBh, gBl, K2, ns*64, nrem);
        }
        CP_COMMIT();
        CP_WAIT2();
        __syncthreads();

        uint32_t sb = sbase + sidx*STG_BYTES;
#pragma unroll
        for (int ks = 0; ks < 2; ks++){
            uint32_t afr[2][2][4];
#pragma unroll
            for (int v = 0; v < 2; v++)
#pragma unroll
                for (int mt = 0; mt < 2; mt++){
                    int row = wm + mt*16 + (lane & 15);
                    int ch  = ((ks*2 + (lane >> 4)) ^ (row & 3)) & 3;
                    ldsm4(afr[v][mt], sb + v*8192 + row*64 + ch*16);
                }
#pragma unroll
            for (int np = 0; np < 4; np++){
                uint32_t bh4[4], bl4[4];
                int row = wn + np*16 + ((lane >> 4) << 3) + (lane & 7);
                int ch  = ((ks*2 + ((lane >> 3) & 1)) ^ (row & 3)) & 3;
                ldsm4(bh4, sb + 16384 + row*64 + ch*16);
                ldsm4(bl4, sb + 24576 + row*64 + ch*16);
#pragma unroll
                for (int mt = 0; mt < 2; mt++){
                    mma16816(acc[mt][np*2],   afr[0][mt], bh4[0], bh4[1]);
                    mma16816(acc[mt][np*2+1], afr[0][mt], bh4[2], bh4[3]);
                }
#pragma unroll
                for (int mt = 0; mt < 2; mt++){
                    mma16816(acc[mt][np*2],   afr[0][mt], bl4[0], bl4[1]);
                    mma16816(acc[mt][np*2+1], afr[0][mt], bl4[2], bl4[3]);
                }
#pragma unroll
                for (int mt = 0; mt < 2; mt++){
                    mma16816(acc[mt][np*2],   afr[1][mt], bh4[0], bh4[1]);
                    mma16816(acc[mt][np*2+1], afr[1][mt], bh4[2], bh4[3]);
                }
            }
        }
        __syncthreads();
        sidx = (sidx + 1 == 3) ? 0 : sidx + 1;
    }

#pragma unroll
    for (int mt = 0; mt < 2; mt++){
        int row = m0 + wm + mt*16 + (lane >> 2);
#pragma unroll
        for (int nt = 0; nt < 8; nt++){
            int col = n0 + wn + nt*8 + (lane & 3)*2;
            if (col < N){
                float* c = acc[mt][nt];
                *(float2*)(C + (size_t)row*N + col)     = make_float2(c[0], c[1]);
                *(float2*)(C + (size_t)(row+8)*N + col) = make_float2(c[2], c[3]);
            }
        }
    }
}

// ---------------- ew_kv (per batch): rmsnorm + k_pe RoPE ----------------
__global__ void __launch_bounds__(256) k_ew(const float* __restrict__ fc,
                                            const float* __restrict__ knw, int batch)
{
    __shared__ float red[8];
    __shared__ float rsv;
    const int s   = blockIdx.x;
    const int m   = batch * S_ + s;
    const int tid = threadIdx.x;
    const float* kvrow = g_kv + (size_t)m * NKV_;

    float v0 = kvrow[tid];
    float v1 = kvrow[tid + 256];
    float ss = v0 * v0 + v1 * v1;
#pragma unroll
    for (int o = 16; o; o >>= 1) ss += __shfl_xor_sync(0xffffffffu, ss, o);
    if ((tid & 31) == 0) red[tid >> 5] = ss;
    __syncthreads();
    if (tid == 0) {
        float tt = 0.f;
#pragma unroll
        for (int i = 0; i < 8; i++) tt += red[i];
        rsv = rsqrtf(tt / (float)RANK_ + 1e-6f);
    }
    __syncthreads();
    const float rs = rsv;
    {
        float y0 = v0 * rs * knw[tid];
        float y1 = v1 * rs * knw[tid + 256];
        size_t o0 = (size_t)m * RANK_ + tid;
        __nv_bfloat16 h, l;
        split_bf16(y0, h, l); g_kvnh[o0]       = h; g_kvnl[o0]       = l;
        split_bf16(y1, h, l); g_kvnh[o0 + 256] = h; g_kvnl[o0 + 256] = l;
    }

    if (tid < 32) {
        float c  = fc[(size_t)s * 64 + 2 * tid];
        float sn = fc[(size_t)s * 64 + 2 * tid + 1];
        float x0 = kvrow[RANK_ + 2 * tid];
        float x1 = kvrow[RANK_ + 2 * tid + 1];
        g_kpe[(size_t)m * 64 + 2 * tid]     = x0 * c - x1 * sn;
        g_kpe[(size_t)m * 64 + 2 * tid + 1] = x0 * sn + x1 * c;
    }
}

// ---------------- Q/K/V conversion (per batch); q-RoPE fused -----------------
#define QSCALE 0.104117565f

__global__ void __launch_bounds__(256) k_qkvcvt(const float* __restrict__ fc, int batch)
{
    const int s = blockIdx.x;
    const int m = batch * S_ + s;
    const int b = batch;
    const int tid = threadIdx.x;
    __nv_bfloat16 H, L;

    for (int p = tid; p < 16*96; p += 256){
        int hh = p / 96, dp = p - hh*96;
        int d = 2*dp;
        size_t qi = (size_t)m * NQ_ + hh*192 + d;
        float x0 = g_q[qi], x1 = g_q[qi + 1];
        float y0, y1;
        if (d < 128){ y0 = x0; y1 = x1; }
        else {
            int i = (d - 128) >> 1;
            float c  = fc[(size_t)s * 64 + 2*i];
            float sn = fc[(size_t)s * 64 + 2*i + 1];
            y0 = x0 * c - x1 * sn;
            y1 = x0 * sn + x1 * c;
        }
        uint32_t hi, lo;
        pksplit(y0 * QSCALE, y1 * QSCALE, hi, lo);
        size_t o = ((size_t)(b*16 + hh) * S_ + s) * 192 + d;
        *(uint32_t*)(g_qh + o) = hi;
        *(uint32_t*)(g_ql + o) = lo;
    }
    for (int i = tid; i < 16*192; i += 256){
        int hh = i / 192, d = i - hh*192;
        size_t o = ((size_t)(b*16 + hh) * S_ + s) * 192 + d;
        float kvv = (d < 128) ? g_kvup[(size_t)m * NUP_ + hh*256 + d]
                              : g_kpe[(size_t)m * 64 + d - 128];
        split_bf16(kvv, H, L); g_kh[o] = H; g_kl[o] = L;
    }
    for (int i = tid; i < 16*128; i += 256){
        int hh = i >> 7, d = i & 127;
        float vv = g_kvup[(size_t)m * NUP_ + hh*256 + 128 + d];
        split_bf16(vv, H, L);
        size_t o = ((size_t)(b*16 + hh) * S_ + s) * 128 + d;
        g_vh[o] = H; g_vl[o] = L;
    }
}

// ---------------- HMMA flash attention v4 (per batch): 2 CTAs/SM ------------
#define A4_KH 0
#define A4_KL 24576
#define A4_VH 49152
#define A4_VL 65536
#define A4_QL 81920
#define ATT4_SMEM 106496

__device__ __forceinline__ uint32_t swzK(int r, int c){
    return (uint32_t)(r*384 + (((c & ~7) | ((c & 7) ^ (r & 7))) << 4));
}
__device__ __forceinline__ uint32_t swzV(int r, int c){
    return (uint32_t)(r*256 + (((c & 8) | ((c & 7) ^ (r & 7))) << 4));
}

__global__ void __launch_bounds__(128, 2) k_attn4(int batch)
{
    extern __shared__ char sm[];
    uint32_t sb = smem_u32(sm);
    const int tid = threadIdx.x, wid = tid >> 5, lane = tid & 31;
    const int h  = blockIdx.y;
    const int b  = batch;
    const int bh = b*16 + h;
    const int qi = gridDim.x - 1 - blockIdx.x;
    const int qb = qi * 64;
    const int nt = qi + 1;

    const __nv_bfloat16* gqh = g_qh + ((size_t)bh * S_ + qb) * 192;
    const __nv_bfloat16* gql = g_ql + ((size_t)bh * S_ + qb) * 192;
    const __nv_bfloat16* gkh = g_kh + (size_t)bh * S_ * 192;
    const __nv_bfloat16* gkl = g_kl + (size_t)bh * S_ * 192;
    const __nv_bfloat16* gvh = g_vh + (size_t)bh * S_ * 128;
    const __nv_bfloat16* gvl = g_vl + (size_t)bh * S_ * 128;

#pragma unroll
    for (int p = 0; p < 12; p++){
        int i = tid + p*128;
        int r = i / 24, c = i - r*24;
        uint32_t so = swzK(r, c);
        cpa16(sb + A4_KH + so, (const char*)gqh + (size_t)r*384 + c*16, 16);
        cpa16(sb + A4_QL + so, (const char*)gql + (size_t)r*384 + c*16, 16);
    }
    CP_COMMIT(); CP_WAIT0();
    __syncthreads();

    uint32_t qh[12][4];
    {
        int row = wid*16 + (lane & 15);
#pragma unroll
        for (int kc = 0; kc < 12; kc++){
            int c = 2*kc + (lane >> 4);
            ldsm4(qh[kc], sb + A4_KH + swzK(row, c));
        }
    }

    float oacc[16][4];
#pragma unroll
    for (int n = 0; n < 16; n++)
#pragma unroll
        for (int c = 0; c < 4; c++) oacc[n][c] = 0.f;
    float m0 = -CUDART_INF_F, m1 = -CUDART_INF_F, l0 = 0.f, l1 = 0.f;

    const int qr0 = qb + wid*16 + (lane >> 2);
    const int koff = 2*(lane & 3);
    const int qrow = wid*16 + (lane & 15);

    for (int t = 0; t < nt; t++){
        __syncthreads();
        {
            const int kb0 = t*64;
#pragma unroll
            for (int p = 0; p < 12; p++){
                int i = tid + p*128;
                int r = i / 24, c = i - r*24;
                uint32_t so = swzK(r, c);
                cpa16(sb + A4_KH + so, (const char*)(gkh + (size_t)(kb0 + r)*192) + c*16, 16);
                cpa16(sb + A4_KL + so, (const char*)(gkl + (size_t)(kb0 + r)*192) + c*16, 16);
            }
#pragma unroll
            for (int p = 0; p < 8; p++){
                int i = tid + p*128;
                int r = i >> 4, c = i & 15;
                uint32_t so = swzV(r, c);
                cpa16(sb + A4_VH + so, (const char*)(gvh + (size_t)(kb0 + r)*128) + c*16, 16);
                cpa16(sb + A4_VL + so, (const char*)(gvl + (size_t)(kb0 + r)*128) + c*16, 16);
            }
        }
        CP_COMMIT(); CP_WAIT0();
        __syncthreads();

        float sacc[8][4];
#pragma unroll
        for (int j = 0; j < 8; j++)
#pragma unroll
            for (int c = 0; c < 4; c++) sacc[j][c] = 0.f;

#pragma unroll
        for (int kc = 0; kc < 12; kc++){
            uint32_t qlf[4];
            {
                int c = 2*kc + (lane >> 4);
                ldsm4(qlf, sb + A4_QL + swzK(qrow, c));
            }
#pragma unroll
            for (int g = 0; g < 4; g++){
                int rowb = g*16 + ((lane >> 4) << 3) + (lane & 7);
                int c = 2*kc + ((lane >> 3) & 1);
                uint32_t so = swzK(rowb, c);
                uint32_t kh4[4], kl4[4];
                ldsm4(kh4, sb + A4_KH + so);
                ldsm4(kl4, sb + A4_KL + so);
                mma16816(sacc[2*g],   qh[kc], kh4[0], kh4[1]);
                mma16816(sacc[2*g+1], qh[kc], kh4[2], kh4[3]);
                mma16816(sacc[2*g],   qlf,    kh4[0], kh4[1]);
                mma16816(sacc[2*g+1], qlf,    kh4[2], kh4[3]);
                mma16816(sacc[2*g],   qh[kc], kl4[0], kl4[1]);
                mma16816(sacc[2*g+1], qh[kc], kl4[2], kl4[3]);
            }
        }

        const int kb = t*64;
        if (kb + 63 > qr0){
#pragma unroll
            for (int j = 0; j < 8; j++){
                if (kb + koff + 8*j     > qr0) sacc[j][0] = -CUDART_INF_F;
                if (kb + koff + 8*j + 1 > qr0) sacc[j][1] = -CUDART_INF_F;
            }
        }
        if (kb + 63 > qr0 + 8){
#pragma unroll
            for (int j = 0; j < 8; j++){
                if (kb + koff + 8*j     > qr0 + 8) sacc[j][2] = -CUDART_INF_F;
                if (kb + koff + 8*j + 1 > qr0 + 8) sacc[j][3] = -CUDART_INF_F;
            }
        }

        float mt0 = -CUDART_INF_F, mt1 = -CUDART_INF_F;
#pragma unroll
        for (int j = 0; j < 8; j++){
            mt0 = fmaxf(mt0, fmaxf(sacc[j][0], sacc[j][1]));
            mt1 = fmaxf(mt1, fmaxf(sacc[j][2], sacc[j][3]));
        }
        mt0 = fmaxf(mt0, __shfl_xor_sync(0xffffffffu, mt0, 1));
        mt0 = fmaxf(mt0, __shfl_xor_sync(0xffffffffu, mt0, 2));
        mt1 = fmaxf(mt1, __shfl_xor_sync(0xffffffffu, mt1, 1));
        mt1 = fmaxf(mt1, __shfl_xor_sync(0xffffffffu, mt1, 2));
        float nm0 = fmaxf(m0, mt0), nm1 = fmaxf(m1, mt1);
        float f0 = ex2f(m0 - nm0);
        float f1 = ex2f(m1 - nm1);
        float ps0 = 0.f, ps1 = 0.f;
#pragma unroll
        for (int j = 0; j < 8; j++){
            sacc[j][0] = ex2f(sacc[j][0] - nm0); ps0 += sacc[j][0];
            sacc[j][1] = ex2f(sacc[j][1] - nm0); ps0 += sacc[j][1];
            sacc[j][2] = ex2f(sacc[j][2] - nm1); ps1 += sacc[j][2];
            sacc[j][3] = ex2f(sacc[j][3] - nm1); ps1 += sacc[j][3];
        }
        ps0 += __shfl_xor_sync(0xffffffffu, ps0, 1);
        ps0 += __shfl_xor_sync(0xffffffffu, ps0, 2);
        ps1 += __shfl_xor_sync(0xffffffffu, ps1, 1);
        ps1 += __shfl_xor_sync(0xffffffffu, ps1, 2);
        l0 = l0*f0 + ps0; l1 = l1*f1 + ps1;
        m0 = nm0; m1 = nm1;

#pragma unroll
        for (int n = 0; n < 16; n++){
            oacc[n][0] *= f0; oacc[n][1] *= f0;
            oacc[n][2] *= f1; oacc[n][3] *= f1;
        }

        uint32_t ph[4][4], pl[4][4];
#pragma unroll
        for (int tt = 0; tt < 4; tt++){
            pksplit(sacc[2*tt][0],   sacc[2*tt][1],   ph[tt][0], pl[tt][0]);
            pksplit(sacc[2*tt][2],   sacc[2*tt][3],   ph[tt][1], pl[tt][1]);
            pksplit(sacc[2*tt+1][0], sacc[2*tt+1][1], ph[tt][2], pl[tt][2]);
            pksplit(sacc[2*tt+1][2], sacc[2*tt+1][3], ph[tt][3], pl[tt][3]);
        }

#pragma unroll
        for (int tt = 0; tt < 4; tt++){
            int rowv = tt*16 + ((lane & 7) | (((lane >> 3) & 1) << 3));
#pragma unroll
            for (int g = 0; g < 8; g++){
                int c = 2*g + (lane >> 4);
                uint32_t so = swzV(rowv, c);
                uint32_t vh4[4], vl4[4];
                ldsm4t(vh4, sb + A4_VH + so);
                ldsm4t(vl4, sb + A4_VL + so);
                mma16816(oacc[2*g],   ph[tt], vh4[0], vh4[1]);
                mma16816(oacc[2*g+1], ph[tt], vh4[2], vh4[3]);
                mma16816(oacc[2*g],   pl[tt], vh4[0], vh4[1]);
                mma16816(oacc[2*g+1], pl[tt], vh4[2], vh4[3]);
                mma16816(oacc[2*g],   ph[tt], vl4[0], vl4[1]);
                mma16816(oacc[2*g+1], ph[tt], vl4[2], vl4[3]);
            }
        }
    }

    float il0 = 1.0f / l0, il1 = 1.0f / l1;
    const int r0 = qb + wid*16 + (lane >> 2);
    size_t ro0 = (size_t)(b*S_ + r0) * NO_ + h*128;
    size_t ro1 = (size_t)(b*S_ + r0 + 8) * NO_ + h*128;
#pragma unroll
    for (int n = 0; n < 16; n++){
        int col = n*8 + 2*(lane & 3);
        uint32_t hi, lo;
        pksplit(oacc[n][0]*il0, oacc[n][1]*il0, hi, lo);
        *(uint32_t*)(g_ath + ro0 + col) = hi;
        *(uint32_t*)(g_atl + ro0 + col) = lo;
        pksplit(oacc[n][2]*il1, oacc[n][3]*il1, hi, lo);
        *(uint32_t*)(g_ath + ro1 + col) = hi;
        *(uint32_t*)(g_atl + ro1 + col) = lo;
    }
}

// ---------------- launch: batch-pipelined, 3 streams ----------------
static void* sym_addr(const void* s) { void* p = nullptr; cudaGetSymbolAddress(&p, s); return p; }

extern "C" void kernel_launch(void* const* d_in, const int* in_sizes, int n_in,
                              void* d_out, int out_size)
{
    const float* x   = (const float*)d_in[0];
    const float* fc  = (const float*)d_in[2];
    const float* wq  = (const float*)d_in[4];
    const float* wa  = (const float*)d_in[5];
    const float* wb  = (const float*)d_in[6];
    const float* wo  = (const float*)d_in[7];
    const float* knw = (const float*)d_in[8];
    float* out = (float*)d_out;

    cudaFuncSetAttribute(k_mmagemm, cudaFuncAttributeMaxDynamicSharedMemorySize, GEMM_SMEM);
    cudaFuncSetAttribute(k_attn4,   cudaFuncAttributeMaxDynamicSharedMemorySize, ATT4_SMEM);

    static cudaStream_t s1 = nullptr, s2 = nullptr;
    static cudaEvent_t evX0, evX1, evQ0, evKV0, evKV1, evWO, evE1, evE2;
    if (!s1){
        cudaStreamCreateWithFlags(&s1, cudaStreamNonBlocking);
        cudaStreamCreateWithFlags(&s2, cudaStreamNonBlocking);
        cudaEventCreateWithFlags(&evX0,  cudaEventDisableTiming);
        cudaEventCreateWithFlags(&evX1,  cudaEventDisableTiming);
        cudaEventCreateWithFlags(&evQ0,  cudaEventDisableTiming);
        cudaEventCreateWithFlags(&evKV0, cudaEventDisableTiming);
        cudaEventCreateWithFlags(&evKV1, cudaEventDisableTiming);
        cudaEventCreateWithFlags(&evWO,  cudaEventDisableTiming);
        cudaEventCreateWithFlags(&evE1,  cudaEventDisableTiming);
        cudaEventCreateWithFlags(&evE2,  cudaEventDisableTiming);
    }

    __nv_bfloat16 *xh  = (__nv_bfloat16*)sym_addr(g_xh),  *xl  = (__nv_bfloat16*)sym_addr(g_xl);
    __nv_bfloat16 *wqh = (__nv_bfloat16*)sym_addr(g_wqh), *wql = (__nv_bfloat16*)sym_addr(g_wql);
    __nv_bfloat16 *wah = (__nv_bfloat16*)sym_addr(g_wah), *wal = (__nv_bfloat16*)sym_addr(g_wal);
    __nv_bfloat16 *wbh = (__nv_bfloat16*)sym_addr(g_wbh), *wbl = (__nv_bfloat16*)sym_addr(g_wbl);
    __nv_bfloat16 *woh = (__nv_bfloat16*)sym_addr(g_woh), *wol = (__nv_bfloat16*)sym_addr(g_wol);
    __nv_bfloat16 *kvh = (__nv_bfloat16*)sym_addr(g_kvnh),*kvl = (__nv_bfloat16*)sym_addr(g_kvnl);
    __nv_bfloat16 *ath = (__nv_bfloat16*)sym_addr(g_ath), *atl = (__nv_bfloat16*)sym_addr(g_atl);
    float *qf  = (float*)sym_addr(g_q);
    float *kvf = (float*)sym_addr(g_kv);
    float *kup = (float*)sym_addr(g_kvup);

    const size_t XB  = (size_t)S_ * DIM_;     // x elems per batch
    const size_t QB  = (size_t)S_ * NQ_;
    const size_t KVB = (size_t)S_ * NKV_;
    const size_t KNB = (size_t)S_ * RANK_;
    const size_t UPB = (size_t)S_ * NUP_;
    const size_t AOB = (size_t)S_ * NO_;

    dim3 t(256);

    // --- s0: cvt_x per batch
    k_cvt<<<XB/1024, t>>>(x,      xh,      xl,      (int)XB);
    cudaEventRecord(evX0, 0);
    k_cvt<<<XB/1024, t>>>(x + XB, xh + XB, xl + XB, (int)XB);
    cudaEventRecord(evX1, 0);

    // --- s1: wq cvt, then gemm_q per batch
    k_cvt<<<(NQ_*DIM_)/1024, t, 0, s1>>>(wq, wqh, wql, NQ_*DIM_);
    cudaStreamWaitEvent(s1, evX0, 0);
    k_mmagemm<<<dim3(NQ_/128, S_/128), t, GEMM_SMEM, s1>>>(xh, xl, wqh, wql, qf, S_, NQ_, DIM_);
    cudaEventRecord(evQ0, s1);

    // --- s0: kv chain b0
    k_cvt<<<(NKV_*DIM_)/1024, t>>>(wa, wah, wal, NKV_*DIM_);
    k_mmagemm<<<dim3((NKV_+127)/128, S_/128), t, GEMM_SMEM>>>(xh, xl, wah, wal, kvf, S_, NKV_, DIM_);
    k_ew<<<S_, 256>>>(fc, knw, 0);
    k_cvt<<<(NUP_*RANK_)/1024, t>>>(wb, wbh, wbl, NUP_*RANK_);
    k_mmagemm<<<dim3(NUP_/128, S_/128), t, GEMM_SMEM>>>(kvh, kvl, wbh, wbl, kup, S_, NUP_, RANK_);
    cudaEventRecord(evKV0, 0);

    // --- s0: kv chain b1
    k_mmagemm<<<dim3((NKV_+127)/128, S_/128), t, GEMM_SMEM>>>(xh + XB, xl + XB, wah, wal,
                                                              kvf + KVB, S_, NKV_, DIM_);
    k_ew<<<S_, 256>>>(fc, knw, 1);
    k_mmagemm<<<dim3(NUP_/128, S_/128), t, GEMM_SMEM>>>(kvh + KNB, kvl + KNB, wbh, wbl,
                                                        kup + UPB, S_, NUP_, RANK_);
    cudaEventRecord(evKV1, 0);

    // --- s0: wo cvt
    k_cvt<<<(DIM_*NO_)/1024, t>>>(wo, woh, wol, DIM_*NO_);
    cudaEventRecord(evWO, 0);

    // --- s1: gemm_q b1, then b1 tail
    cudaStreamWaitEvent(s1, evX1, 0);
    k_mmagemm<<<dim3(NQ_/128, S_/128), t, GEMM_SMEM, s1>>>(xh + XB, xl + XB, wqh, wql,
                                                           qf + QB, S_, NQ_, DIM_);
    cudaStreamWaitEvent(s1, evKV1, 0);
    k_qkvcvt<<<S_, 256, 0, s1>>>(fc, 1);
    k_attn4<<<dim3(S_/64, NH_), dim3(128), ATT4_SMEM, s1>>>(1);
    cudaStreamWaitEvent(s1, evWO, 0);
    k_mmagemm<<<dim3(DIM_/128, S_/128), t, GEMM_SMEM, s1>>>(
        ath + AOB, atl + AOB, woh, wol, out + (size_t)S_*DIM_, S_, DIM_, NO_);
    cudaEventRecord(evE1, s1);

    // --- s2: b0 tail (starts as soon as gemm_q_b0 + kvup_b0 done)
    cudaStreamWaitEvent(s2, evQ0, 0);
    cudaStreamWaitEvent(s2, evKV0, 0);
    k_qkvcvt<<<S_, 256, 0, s2>>>(fc, 0);
    k_attn4<<<dim3(S_/64, NH_), dim3(128), ATT4_SMEM, s2>>>(0);
    cudaStreamWaitEvent(s2, evWO, 0);
    k_mmagemm<<<dim3(DIM_/128, S_/128), t, GEMM_SMEM, s2>>>(ath, atl, woh, wol, out, S_, DIM_, NO_);
    cudaEventRecord(evE2, s2);

    // --- join back to stream 0
    cudaStreamWaitEvent(0, evE1, 0);
    cudaStreamWaitEvent(0, evE2, 0);
}

// round 12
// speedup vs baseline: 1.0703x; 1.0703x over previous
#include <cuda_runtime.h>
#include <cuda_bf16.h>
#include <math_constants.h>
#include <cstdint>

// ---------------- problem constants ----------------
#define B_    2
#define S_    2048
#define DIM_  2048
#define NH_   16
#define DQK_  192
#define DNOPE_ 128
#define DROPE_ 64
#define DV_   128
#define RANK_ 512
#define M_    (B_*S_)          // 4096
#define NQ_   (NH_*DQK_)       // 3072
#define NKV_  (RANK_+DROPE_)   // 576
#define NUP_  (NH_*(DNOPE_+DV_)) // 4096
#define NO_   (NH_*DV_)        // 2048

// ---------------- scratch (device globals; no allocs allowed) ----------------
__device__ __nv_bfloat16 g_xh [M_*DIM_],  g_xl [M_*DIM_];
__device__ __nv_bfloat16 g_wqh[NQ_*DIM_], g_wql[NQ_*DIM_];
__device__ __nv_bfloat16 g_wah[NKV_*DIM_],g_wal[NKV_*DIM_];
__device__ __nv_bfloat16 g_wbh[NUP_*RANK_],g_wbl[NUP_*RANK_];
__device__ __nv_bfloat16 g_woh[DIM_*NO_], g_wol[DIM_*NO_];
__device__ __nv_bfloat16 g_kvnh[M_*RANK_],g_kvnl[M_*RANK_];
__device__ __nv_bfloat16 g_ath[M_*NO_],   g_atl[M_*NO_];
__device__ float g_q   [M_*NQ_];
__device__ float g_kv  [M_*NKV_];
__device__ float g_kpe [M_*DROPE_];
__device__ float g_kvup[M_*NUP_];
// head-major bf16 hi/lo operands for attention
__device__ __nv_bfloat16 g_qh[B_*NH_*S_*DQK_], g_ql[B_*NH_*S_*DQK_];
__device__ __nv_bfloat16 g_kh[B_*NH_*S_*DQK_], g_kl[B_*NH_*S_*DQK_];
__device__ __nv_bfloat16 g_vh[B_*NH_*S_*DV_],  g_vl[B_*NH_*S_*DV_];

// ---------------- PTX helpers ----------------
__device__ __forceinline__ uint32_t smem_u32(const void* p){
    uint32_t a;
    asm("{ .reg .u64 t; cvta.to.shared.u64 t, %1; cvt.u32.u64 %0, t; }"
        : "=r"(a) : "l"(p));
    return a;
}
__device__ __forceinline__ void cpa16(uint32_t dst, const void* src, int sz){
    asm volatile("cp.async.cg.shared.global [%0], [%1], 16, %2;"
                 :: "r"(dst), "l"(src), "r"(sz) : "memory");
}
#define CP_COMMIT() asm volatile("cp.async.commit_group;" ::: "memory")
#define CP_WAIT2()  asm volatile("cp.async.wait_group 2;" ::: "memory")
#define CP_WAIT0()  asm volatile("cp.async.wait_group 0;" ::: "memory")

__device__ __forceinline__ void ldsm4(uint32_t* r, uint32_t addr){
    asm volatile("ldmatrix.sync.aligned.m8n8.x4.shared.b16 {%0,%1,%2,%3}, [%4];"
        : "=r"(r[0]), "=r"(r[1]), "=r"(r[2]), "=r"(r[3]) : "r"(addr));
}
__device__ __forceinline__ void ldsm4t(uint32_t* r, uint32_t addr){
    asm volatile("ldmatrix.sync.aligned.m8n8.x4.trans.shared.b16 {%0,%1,%2,%3}, [%4];"
        : "=r"(r[0]), "=r"(r[1]), "=r"(r[2]), "=r"(r[3]) : "r"(addr));
}
__device__ __forceinline__ void mma16816(float* c, const uint32_t* a,
                                         uint32_t b0, uint32_t b1){
    asm volatile("mma.sync.aligned.m16n8k16.row.col.f32.bf16.bf16.f32 "
        "{%0,%1,%2,%3}, {%4,%5,%6,%7}, {%8,%9}, {%0,%1,%2,%3};"
        : "+f"(c[0]), "+f"(c[1]), "+f"(c[2]), "+f"(c[3])
        : "r"(a[0]), "r"(a[1]), "r"(a[2]), "r"(a[3]), "r"(b0), "r"(b1));
}
__device__ __forceinline__ float ex2f(float x){
    float y; asm("ex2.approx.ftz.f32 %0, %1;" : "=f"(y) : "f"(x)); return y;
}

// ---------------- hi/lo bf16 split ----------------
__device__ __forceinline__ void split_bf16(float v, __nv_bfloat16& h, __nv_bfloat16& l){
    h = __float2bfloat16(v);
    l = __float2bfloat16(v - __bfloat162float(h));
}
__device__ __forceinline__ void pksplit(float a, float b, uint32_t& hi, uint32_t& lo){
    __nv_bfloat16 ah, al, bh, bl;
    split_bf16(a, ah, al); split_bf16(b, bh, bl);
    __nv_bfloat162 H; H.x = ah; H.y = bh; hi = *(uint32_t*)&H;
    __nv_bfloat162 L; L.x = al; L.y = bl; lo = *(uint32_t*)&L;
}

__global__ void __launch_bounds__(256) k_cvt(const float* __restrict__ s,
                                             __nv_bfloat16* __restrict__ h,
                                             __nv_bfloat16* __restrict__ l, int n)
{
    int i = (blockIdx.x * 256 + threadIdx.x) * 4;
    if (i >= n) return;
    float4 v = *(const float4*)(s + i);
    __nv_bfloat16 h0, l0, h1, l1, h2, l2, h3, l3;
    split_bf16(v.x, h0, l0); split_bf16(v.y, h1, l1);
    split_bf16(v.z, h2, l2); split_bf16(v.w, h3, l3);
    __nv_bfloat162 p;
    p.x = h0; p.y = h1; *(__nv_bfloat162*)(h + i)     = p;
    p.x = h2; p.y = h3; *(__nv_bfloat162*)(h + i + 2) = p;
    p.x = l0; p.y = l1; *(__nv_bfloat162*)(l + i)     = p;
    p.x = l2; p.y = l3; *(__nv_bfloat162*)(l + i + 2) = p;
}

// ---------------- mma.sync GEMM (R6 proven config) ------------------
#define STG_BYTES 32768
#define GEMM_SMEM (3*STG_BYTES)

__device__ __forceinline__ void stage_load(uint32_t sdst,
    const char* ah, const char* al, const char* bh, const char* bl,
    int K2, int k0b, int nrem)
{
    const int tid = threadIdx.x;
#pragma unroll
    for (int p = 0; p < 2; p++){
        int idx = tid + p*256;
        int r = idx >> 2, c = idx & 3;
        uint32_t soff = (uint32_t)(r*64 + ((c ^ (r & 3)) << 4));
        size_t go = (size_t)r * K2 + k0b + c*16;
        cpa16(sdst + soff,        ah + go, 16);
        cpa16(sdst + 8192 + soff, al + go, 16);
        int rb = (r < nrem) ? r : 0;
        int sz = (r < nrem) ? 16 : 0;
        size_t gob = (size_t)rb * K2 + k0b + c*16;
        cpa16(sdst + 16384 + soff, bh + gob, sz);
        cpa16(sdst + 24576 + soff, bl + gob, sz);
    }
}

__global__ void __launch_bounds__(256, 2)
k_mmagemm(const __nv_bfloat16* __restrict__ Ah, const __nv_bfloat16* __restrict__ Al,
          const __nv_bfloat16* __restrict__ Bh, const __nv_bfloat16* __restrict__ Bl,
          float* __restrict__ C, int M, int N, int K)
{
    extern __shared__ char smc[];
    const int tid = threadIdx.x, wid = tid >> 5, lane = tid & 31;
    const int m0 = blockIdx.y * 128, n0 = blockIdx.x * 128;
    const int wm = (wid & 3) * 32, wn = (wid >> 2) * 64;
    const int nrem = N - n0;
    const int K2 = K * 2;
    const int nk = K / 32;

    uint32_t sbase = smem_u32(smc);
    const char* gAh = (const char*)(Ah + (size_t)m0 * K);
    const char* gAl = (const char*)(Al + (size_t)m0 * K);
    const char* gBh = (const char*)(Bh + (size_t)n0 * K);
    const char* gBl = (const char*)(Bl + (size_t)n0 * K);

#pragma unroll
    for (int s = 0; s < 2; s++){
        stage_load(sbase + s*STG_BYTES, gAh, gAl, gBh, gBl, K2, s*64, nrem);
        CP_COMMIT();
    }

    float acc[2][8][4];
#pragma unroll
    for (int a = 0; a < 2; a++)
#pragma unroll
        for (int b = 0; b < 8; b++)
#pragma unroll
            for (int c = 0; c < 4; c++) acc[a][b][c] = 0.f;

    int sidx = 0;
    for (int kt = 0; kt < nk; kt++){
        int ns = kt + 2;
        if (ns < nk){
            int fs = ns - 3*(ns/3);
            stage_load(sbase + fs*STG_BYTES, gAh, gAl, gBh, gBl, K2, ns*64, nrem);
        }
        CP_COMMIT();
        CP_WAIT2();
        __syncthreads();

        uint32_t sb = sbase + sidx*STG_BYTES;
#pragma unroll
        for (int ks = 0; ks < 2; ks++){
            uint32_t afr[2][2][4];
#pragma unroll
            for (int v = 0; v < 2; v++)
#pragma unroll
                for (int mt = 0; mt < 2; mt++){
                    int row = wm + mt*16 + (lane & 15);
                    int ch  = ((ks*2 + (lane >> 4)) ^ (row & 3)) & 3;
                    ldsm4(afr[v][mt], sb + v*8192 + row*64 + ch*16);
                }
#pragma unroll
            for (int np = 0; np < 4; np++){
                uint32_t bh4[4], bl4[4];
                int row = wn + np*16 + ((lane >> 4) << 3) + (lane & 7);
                int ch  = ((ks*2 + ((lane >> 3) & 1)) ^ (row & 3)) & 3;
                ldsm4(bh4, sb + 16384 + row*64 + ch*16);
                ldsm4(bl4, sb + 24576 + row*64 + ch*16);
#pragma unroll
                for (int mt = 0; mt < 2; mt++){
                    mma16816(acc[mt][np*2],   afr[0][mt], bh4[0], bh4[1]);
                    mma16816(acc[mt][np*2+1], afr[0][mt], bh4[2], bh4[3]);
                }
#pragma unroll
                for (int mt = 0; mt < 2; mt++){
                    mma16816(acc[mt][np*2],   afr[0][mt], bl4[0], bl4[1]);
                    mma16816(acc[mt][np*2+1], afr[0][mt], bl4[2], bl4[3]);
                }
#pragma unroll
                for (int mt = 0; mt < 2; mt++){
                    mma16816(acc[mt][np*2],   afr[1][mt], bh4[0], bh4[1]);
                    mma16816(acc[mt][np*2+1], afr[1][mt], bh4[2], bh4[3]);
                }
            }
        }
        __syncthreads();
        sidx = (sidx + 1 == 3) ? 0 : sidx + 1;
    }

#pragma unroll
    for (int mt = 0; mt < 2; mt++){
        int row = m0 + wm + mt*16 + (lane >> 2);
#pragma unroll
        for (int nt = 0; nt < 8; nt++){
            int col = n0 + wn + nt*8 + (lane & 3)*2;
            if (col < N){
                float* c = acc[mt][nt];
                *(float2*)(C + (size_t)row*N + col)     = make_float2(c[0], c[1]);
                *(float2*)(C + (size_t)(row+8)*N + col) = make_float2(c[2], c[3]);
            }
        }
    }
}

// ---------------- ew_kv: rmsnorm + k_pe RoPE (full M) ----------------
__global__ void __launch_bounds__(256) k_ew(const float* __restrict__ fc,
                                            const float* __restrict__ knw)
{
    __shared__ float red[8];
    __shared__ float rsv;
    const int m   = blockIdx.x;
    const int s   = m & (S_ - 1);
    const int tid = threadIdx.x;
    const float* kvrow = g_kv + (size_t)m * NKV_;

    float v0 = kvrow[tid];
    float v1 = kvrow[tid + 256];
    float ss = v0 * v0 + v1 * v1;
#pragma unroll
    for (int o = 16; o; o >>= 1) ss += __shfl_xor_sync(0xffffffffu, ss, o);
    if ((tid & 31) == 0) red[tid >> 5] = ss;
    __syncthreads();
    if (tid == 0) {
        float tt = 0.f;
#pragma unroll
        for (int i = 0; i < 8; i++) tt += red[i];
        rsv = rsqrtf(tt / (float)RANK_ + 1e-6f);
    }
    __syncthreads();
    const float rs = rsv;
    {
        float y0 = v0 * rs * knw[tid];
        float y1 = v1 * rs * knw[tid + 256];
        size_t o0 = (size_t)m * RANK_ + tid;
        __nv_bfloat16 h, l;
        split_bf16(y0, h, l); g_kvnh[o0]       = h; g_kvnl[o0]       = l;
        split_bf16(y1, h, l); g_kvnh[o0 + 256] = h; g_kvnl[o0 + 256] = l;
    }

    if (tid < 32) {
        float c  = fc[(size_t)s * 64 + 2 * tid];
        float sn = fc[(size_t)s * 64 + 2 * tid + 1];
        float x0 = kvrow[RANK_ + 2 * tid];
        float x1 = kvrow[RANK_ + 2 * tid + 1];
        g_kpe[(size_t)m * 64 + 2 * tid]     = x0 * c - x1 * sn;
        g_kpe[(size_t)m * 64 + 2 * tid + 1] = x0 * sn + x1 * c;
    }
}

// ---------------- Q/K/V conversion (per batch); q-RoPE fused -----------------
#define QSCALE 0.104117565f

__global__ void __launch_bounds__(256) k_qkvcvt(const float* __restrict__ fc, int batch)
{
    const int s = blockIdx.x;
    const int m = batch * S_ + s;
    const int b = batch;
    const int tid = threadIdx.x;
    __nv_bfloat16 H, L;

    for (int p = tid; p < 16*96; p += 256){
        int hh = p / 96, dp = p - hh*96;
        int d = 2*dp;
        size_t qi = (size_t)m * NQ_ + hh*192 + d;
        float x0 = g_q[qi], x1 = g_q[qi + 1];
        float y0, y1;
        if (d < 128){ y0 = x0; y1 = x1; }
        else {
            int i = (d - 128) >> 1;
            float c  = fc[(size_t)s * 64 + 2*i];
            float sn = fc[(size_t)s * 64 + 2*i + 1];
            y0 = x0 * c - x1 * sn;
            y1 = x0 * sn + x1 * c;
        }
        uint32_t hi, lo;
        pksplit(y0 * QSCALE, y1 * QSCALE, hi, lo);
        size_t o = ((size_t)(b*16 + hh) * S_ + s) * 192 + d;
        *(uint32_t*)(g_qh + o) = hi;
        *(uint32_t*)(g_ql + o) = lo;
    }
    for (int i = tid; i < 16*192; i += 256){
        int hh = i / 192, d = i - hh*192;
        size_t o = ((size_t)(b*16 + hh) * S_ + s) * 192 + d;
        float kvv = (d < 128) ? g_kvup[(size_t)m * NUP_ + hh*256 + d]
                              : g_kpe[(size_t)m * 64 + d - 128];
        split_bf16(kvv, H, L); g_kh[o] = H; g_kl[o] = L;
    }
    for (int i = tid; i < 16*128; i += 256){
        int hh = i >> 7, d = i & 127;
        float vv = g_kvup[(size_t)m * NUP_ + hh*256 + 128 + d];
        split_bf16(vv, H, L);
        size_t o = ((size_t)(b*16 + hh) * S_ + s) * 128 + d;
        g_vh[o] = H; g_vl[o] = L;
    }
}

// ---------------- HMMA flash attention v4 (per batch): 2 CTAs/SM ------------
#define A4_KH 0
#define A4_KL 24576
#define A4_VH 49152
#define A4_VL 65536
#define A4_QL 81920
#define ATT4_SMEM 106496

__device__ __forceinline__ uint32_t swzK(int r, int c){
    return (uint32_t)(r*384 + (((c & ~7) | ((c & 7) ^ (r & 7))) << 4));
}
__device__ __forceinline__ uint32_t swzV(int r, int c){
    return (uint32_t)(r*256 + (((c & 8) | ((c & 7) ^ (r & 7))) << 4));
}

__global__ void __launch_bounds__(128, 2) k_attn4(int batch)
{
    extern __shared__ char sm[];
    uint32_t sb = smem_u32(sm);
    const int tid = threadIdx.x, wid = tid >> 5, lane = tid & 31;
    const int h  = blockIdx.y;
    const int b  = batch;
    const int bh = b*16 + h;
    const int qi = gridDim.x - 1 - blockIdx.x;
    const int qb = qi * 64;
    const int nt = qi + 1;

    const __nv_bfloat16* gqh = g_qh + ((size_t)bh * S_ + qb) * 192;
    const __nv_bfloat16* gql = g_ql + ((size_t)bh * S_ + qb) * 192;
    const __nv_bfloat16* gkh = g_kh + (size_t)bh * S_ * 192;
    const __nv_bfloat16* gkl = g_kl + (size_t)bh * S_ * 192;
    const __nv_bfloat16* gvh = g_vh + (size_t)bh * S_ * 128;
    const __nv_bfloat16* gvl = g_vl + (size_t)bh * S_ * 128;

#pragma unroll
    for (int p = 0; p < 12; p++){
        int i = tid + p*128;
        int r = i / 24, c = i - r*24;
        uint32_t so = swzK(r, c);
        cpa16(sb + A4_KH + so, (const char*)gqh + (size_t)r*384 + c*16, 16);
        cpa16(sb + A4_QL + so, (const char*)gql + (size_t)r*384 + c*16, 16);
    }
    CP_COMMIT(); CP_WAIT0();
    __syncthreads();

    uint32_t qh[12][4];
    {
        int row = wid*16 + (lane & 15);
#pragma unroll
        for (int kc = 0; kc < 12; kc++){
            int c = 2*kc + (lane >> 4);
            ldsm4(qh[kc], sb + A4_KH + swzK(row, c));
        }
    }

    float oacc[16][4];
#pragma unroll
    for (int n = 0; n < 16; n++)
#pragma unroll
        for (int c = 0; c < 4; c++) oacc[n][c] = 0.f;
    float m0 = -CUDART_INF_F, m1 = -CUDART_INF_F, l0 = 0.f, l1 = 0.f;

    const int qr0 = qb + wid*16 + (lane >> 2);
    const int koff = 2*(lane & 3);
    const int qrow = wid*16 + (lane & 15);

    for (int t = 0; t < nt; t++){
        __syncthreads();
        {
            const int kb0 = t*64;
#pragma unroll
            for (int p = 0; p < 12; p++){
                int i = tid + p*128;
                int r = i / 24, c = i - r*24;
                uint32_t so = swzK(r, c);
                cpa16(sb + A4_KH + so, (const char*)(gkh + (size_t)(kb0 + r)*192) + c*16, 16);
                cpa16(sb + A4_KL + so, (const char*)(gkl + (size_t)(kb0 + r)*192) + c*16, 16);
            }
#pragma unroll
            for (int p = 0; p < 8; p++){
                int i = tid + p*128;
                int r = i >> 4, c = i & 15;
                uint32_t so = swzV(r, c);
                cpa16(sb + A4_VH + so, (const char*)(gvh + (size_t)(kb0 + r)*128) + c*16, 16);
                cpa16(sb + A4_VL + so, (const char*)(gvl + (size_t)(kb0 + r)*128) + c*16, 16);
            }
        }
        CP_COMMIT(); CP_WAIT0();
        __syncthreads();

        float sacc[8][4];
#pragma unroll
        for (int j = 0; j < 8; j++)
#pragma unroll
            for (int c = 0; c < 4; c++) sacc[j][c] = 0.f;

#pragma unroll
        for (int kc = 0; kc < 12; kc++){
            uint32_t qlf[4];
            {
                int c = 2*kc + (lane >> 4);
                ldsm4(qlf, sb + A4_QL + swzK(qrow, c));
            }
#pragma unroll
            for (int g = 0; g < 4; g++){
                int rowb = g*16 + ((lane >> 4) << 3) + (lane & 7);
                int c = 2*kc + ((lane >> 3) & 1);
                uint32_t so = swzK(rowb, c);
                uint32_t kh4[4], kl4[4];
                ldsm4(kh4, sb + A4_KH + so);
                ldsm4(kl4, sb + A4_KL + so);
                mma16816(sacc[2*g],   qh[kc], kh4[0], kh4[1]);
                mma16816(sacc[2*g+1], qh[kc], kh4[2], kh4[3]);
                mma16816(sacc[2*g],   qlf,    kh4[0], kh4[1]);
                mma16816(sacc[2*g+1], qlf,    kh4[2], kh4[3]);
                mma16816(sacc[2*g],   qh[kc], kl4[0], kl4[1]);
                mma16816(sacc[2*g+1], qh[kc], kl4[2], kl4[3]);
            }
        }

        const int kb = t*64;
        if (kb + 63 > qr0){
#pragma unroll
            for (int j = 0; j < 8; j++){
                if (kb + koff + 8*j     > qr0) sacc[j][0] = -CUDART_INF_F;
                if (kb + koff + 8*j + 1 > qr0) sacc[j][1] = -CUDART_INF_F;
            }
        }
        if (kb + 63 > qr0 + 8){
#pragma unroll
            for (int j = 0; j < 8; j++){
                if (kb + koff + 8*j     > qr0 + 8) sacc[j][2] = -CUDART_INF_F;
                if (kb + koff + 8*j + 1 > qr0 + 8) sacc[j][3] = -CUDART_INF_F;
            }
        }

        float mt0 = -CUDART_INF_F, mt1 = -CUDART_INF_F;
#pragma unroll
        for (int j = 0; j < 8; j++){
            mt0 = fmaxf(mt0, fmaxf(sacc[j][0], sacc[j][1]));
            mt1 = fmaxf(mt1, fmaxf(sacc[j][2], sacc[j][3]));
        }
        mt0 = fmaxf(mt0, __shfl_xor_sync(0xffffffffu, mt0, 1));
        mt0 = fmaxf(mt0, __shfl_xor_sync(0xffffffffu, mt0, 2));
        mt1 = fmaxf(mt1, __shfl_xor_sync(0xffffffffu, mt1, 1));
        mt1 = fmaxf(mt1, __shfl_xor_sync(0xffffffffu, mt1, 2));
        float nm0 = fmaxf(m0, mt0), nm1 = fmaxf(m1, mt1);
        float f0 = ex2f(m0 - nm0);
        float f1 = ex2f(m1 - nm1);
        float ps0 = 0.f, ps1 = 0.f;
#pragma unroll
        for (int j = 0; j < 8; j++){
            sacc[j][0] = ex2f(sacc[j][0] - nm0); ps0 += sacc[j][0];
            sacc[j][1] = ex2f(sacc[j][1] - nm0); ps0 += sacc[j][1];
            sacc[j][2] = ex2f(sacc[j][2] - nm1); ps1 += sacc[j][2];
            sacc[j][3] = ex2f(sacc[j][3] - nm1); ps1 += sacc[j][3];
        }
        ps0 += __shfl_xor_sync(0xffffffffu, ps0, 1);
        ps0 += __shfl_xor_sync(0xffffffffu, ps0, 2);
        ps1 += __shfl_xor_sync(0xffffffffu, ps1, 1);
        ps1 += __shfl_xor_sync(0xffffffffu, ps1, 2);
        l0 = l0*f0 + ps0; l1 = l1*f1 + ps1;
        m0 = nm0; m1 = nm1;

#pragma unroll
        for (int n = 0; n < 16; n++){
            oacc[n][0] *= f0; oacc[n][1] *= f0;
            oacc[n][2] *= f1; oacc[n][3] *= f1;
        }

        uint32_t ph[4][4], pl[4][4];
#pragma unroll
        for (int tt = 0; tt < 4; tt++){
            pksplit(sacc[2*tt][0],   sacc[2*tt][1],   ph[tt][0], pl[tt][0]);
            pksplit(sacc[2*tt][2],   sacc[2*tt][3],   ph[tt][1], pl[tt][1]);
            pksplit(sacc[2*tt+1][0], sacc[2*tt+1][1], ph[tt][2], pl[tt][2]);
            pksplit(sacc[2*tt+1][2], sacc[2*tt+1][3], ph[tt][3], pl[tt][3]);
        }

#pragma unroll
        for (int tt = 0; tt < 4; tt++){
            int rowv = tt*16 + ((lane & 7) | (((lane >> 3) & 1) << 3));
#pragma unroll
            for (int g = 0; g < 8; g++){
                int c = 2*g + (lane >> 4);
                uint32_t so = swzV(rowv, c);
                uint32_t vh4[4], vl4[4];
                ldsm4t(vh4, sb + A4_VH + so);
                ldsm4t(vl4, sb + A4_VL + so);
                mma16816(oacc[2*g],   ph[tt], vh4[0], vh4[1]);
                mma16816(oacc[2*g+1], ph[tt], vh4[2], vh4[3]);
                mma16816(oacc[2*g],   pl[tt], vh4[0], vh4[1]);
                mma16816(oacc[2*g+1], pl[tt], vh4[2], vh4[3]);
                mma16816(oacc[2*g],   ph[tt], vl4[0], vl4[1]);
                mma16816(oacc[2*g+1], ph[tt], vl4[2], vl4[3]);
            }
        }
    }

    float il0 = 1.0f / l0, il1 = 1.0f / l1;
    const int r0 = qb + wid*16 + (lane >> 2);
    size_t ro0 = (size_t)(b*S_ + r0) * NO_ + h*128;
    size_t ro1 = (size_t)(b*S_ + r0 + 8) * NO_ + h*128;
#pragma unroll
    for (int n = 0; n < 16; n++){
        int col = n*8 + 2*(lane & 3);
        uint32_t hi, lo;
        pksplit(oacc[n][0]*il0, oacc[n][1]*il0, hi, lo);
        *(uint32_t*)(g_ath + ro0 + col) = hi;
        *(uint32_t*)(g_atl + ro0 + col) = lo;
        pksplit(oacc[n][2]*il1, oacc[n][3]*il1, hi, lo);
        *(uint32_t*)(g_ath + ro1 + col) = hi;
        *(uint32_t*)(g_atl + ro1 + col) = lo;
    }
}

// ---------------- launch: R10 graph + gemm_q batch split ----------------
static void* sym_addr(const void* s) { void* p = nullptr; cudaGetSymbolAddress(&p, s); return p; }

extern "C" void kernel_launch(void* const* d_in, const int* in_sizes, int n_in,
                              void* d_out, int out_size)
{
    const float* x   = (const float*)d_in[0];
    const float* fc  = (const float*)d_in[2];
    const float* wq  = (const float*)d_in[4];
    const float* wa  = (const float*)d_in[5];
    const float* wb  = (const float*)d_in[6];
    const float* wo  = (const float*)d_in[7];
    const float* knw = (const float*)d_in[8];
    float* out = (float*)d_out;

    cudaFuncSetAttribute(k_mmagemm, cudaFuncAttributeMaxDynamicSharedMemorySize, GEMM_SMEM);
    cudaFuncSetAttribute(k_attn4,   cudaFuncAttributeMaxDynamicSharedMemorySize, ATT4_SMEM);

    static cudaStream_t s1 = nullptr, s2 = nullptr;
    static cudaEvent_t evFork, evQ0, evKV, evWO, evE1, evE2;
    if (!s1){
        cudaStreamCreateWithFlags(&s1, cudaStreamNonBlocking);
        cudaStreamCreateWithFlags(&s2, cudaStreamNonBlocking);
        cudaEventCreateWithFlags(&evFork, cudaEventDisableTiming);
        cudaEventCreateWithFlags(&evQ0,   cudaEventDisableTiming);
        cudaEventCreateWithFlags(&evKV,   cudaEventDisableTiming);
        cudaEventCreateWithFlags(&evWO,   cudaEventDisableTiming);
        cudaEventCreateWithFlags(&evE1,   cudaEventDisableTiming);
        cudaEventCreateWithFlags(&evE2,   cudaEventDisableTiming);
    }

    __nv_bfloat16 *xh  = (__nv_bfloat16*)sym_addr(g_xh),  *xl  = (__nv_bfloat16*)sym_addr(g_xl);
    __nv_bfloat16 *wqh = (__nv_bfloat16*)sym_addr(g_wqh), *wql = (__nv_bfloat16*)sym_addr(g_wql);
    __nv_bfloat16 *wah = (__nv_bfloat16*)sym_addr(g_wah), *wal = (__nv_bfloat16*)sym_addr(g_wal);
    __nv_bfloat16 *wbh = (__nv_bfloat16*)sym_addr(g_wbh), *wbl = (__nv_bfloat16*)sym_addr(g_wbl);
    __nv_bfloat16 *woh = (__nv_bfloat16*)sym_addr(g_woh), *wol = (__nv_bfloat16*)sym_addr(g_wol);
    __nv_bfloat16 *kvh = (__nv_bfloat16*)sym_addr(g_kvnh),*kvl = (__nv_bfloat16*)sym_addr(g_kvnl);
    __nv_bfloat16 *ath = (__nv_bfloat16*)sym_addr(g_ath), *atl = (__nv_bfloat16*)sym_addr(g_atl);
    float *qf  = (float*)sym_addr(g_q);
    float *kvf = (float*)sym_addr(g_kv);
    float *kup = (float*)sym_addr(g_kvup);

    const size_t XB  = (size_t)S_ * DIM_;
    const size_t QB  = (size_t)S_ * NQ_;
    const size_t AOB = (size_t)S_ * NO_;

    dim3 t(256);

    // --- s0: x + wa conversions (full), then fork
    k_cvt<<<(M_*DIM_)/1024,   t>>>(x,  xh,  xl,  M_*DIM_);
    k_cvt<<<(NKV_*DIM_)/1024, t>>>(wa, wah, wal, NKV_*DIM_);
    cudaEventRecord(evFork, 0);
    cudaStreamWaitEvent(s1, evFork, 0);

    // --- s1: wq cvt -> gemm_q b0 (evQ0) -> gemm_q b1
    k_cvt<<<(NQ_*DIM_)/1024, t, 0, s1>>>(wq, wqh, wql, NQ_*DIM_);
    k_mmagemm<<<dim3(NQ_/128, S_/128), t, GEMM_SMEM, s1>>>(xh, xl, wqh, wql, qf, S_, NQ_, DIM_);
    cudaEventRecord(evQ0, s1);
    k_mmagemm<<<dim3(NQ_/128, S_/128), t, GEMM_SMEM, s1>>>(xh + XB, xl + XB, wqh, wql,
                                                           qf + QB, S_, NQ_, DIM_);

    // --- s0: full kv chain (concurrent with gemm_q), then wo cvt
    k_mmagemm<<<dim3((NKV_+127)/128, M_/128), t, GEMM_SMEM>>>(xh, xl, wah, wal, kvf, M_, NKV_, DIM_);
    k_ew<<<M_, 256>>>(fc, knw);
    k_cvt<<<(NUP_*RANK_)/1024, t>>>(wb, wbh, wbl, NUP_*RANK_);
    k_mmagemm<<<dim3(NUP_/128, M_/128), t, GEMM_SMEM>>>(kvh, kvl, wbh, wbl, kup, M_, NUP_, RANK_);
    cudaEventRecord(evKV, 0);
    k_cvt<<<(DIM_*NO_)/1024, t>>>(wo, woh, wol, DIM_*NO_);
    cudaEventRecord(evWO, 0);

    // --- s2: b0 tail (starts after gemm_q_b0 + kvup; overlaps gemm_q_b1)
    cudaStreamWaitEvent(s2, evQ0, 0);
    cudaStreamWaitEvent(s2, evKV, 0);
    k_qkvcvt<<<S_, 256, 0, s2>>>(fc, 0);
    k_attn4<<<dim3(S_/64, NH_), dim3(128), ATT4_SMEM, s2>>>(0);
    cudaStreamWaitEvent(s2, evWO, 0);
    k_mmagemm<<<dim3(DIM_/128, S_/128), t, GEMM_SMEM, s2>>>(ath, atl, woh, wol, out, S_, DIM_, NO_);
    cudaEventRecord(evE2, s2);

    // --- s1: b1 tail (after gemm_q_b1; needs kvup)
    cudaStreamWaitEvent(s1, evKV, 0);
    k_qkvcvt<<<S_, 256, 0, s1>>>(fc, 1);
    k_attn4<<<dim3(S_/64, NH_), dim3(128), ATT4_SMEM, s1>>>(1);
    cudaStreamWaitEvent(s1, evWO, 0);
    k_mmagemm<<<dim3(DIM_/128, S_/128), t, GEMM_SMEM, s1>>>(
        ath + AOB, atl + AOB, woh, wol, out + (size_t)S_*DIM_, S_, DIM_, NO_);
    cudaEventRecord(evE1, s1);

    // --- join
    cudaStreamWaitEvent(0, evE1, 0);
    cudaStreamWaitEvent(0, evE2, 0);
}

// round 13
// speedup vs baseline: 1.1109x; 1.0379x over previous
#include <cuda_runtime.h>
#include <cuda_bf16.h>
#include <math_constants.h>
#include <cstdint>

// ---------------- problem constants ----------------
#define B_    2
#define S_    2048
#define DIM_  2048
#define NH_   16
#define DQK_  192
#define DNOPE_ 128
#define DROPE_ 64
#define DV_   128
#define RANK_ 512
#define M_    (B_*S_)          // 4096
#define NQ_   (NH_*DQK_)       // 3072
#define NKV_  (RANK_+DROPE_)   // 576
#define NUP_  (NH_*(DNOPE_+DV_)) // 4096
#define NO_   (NH_*DV_)        // 2048
#define QSCALE 0.104117565f    // (1/sqrt(192)) * log2(e)

// ---------------- scratch (device globals; no allocs allowed) ----------------
__device__ __nv_bfloat16 g_xh [M_*DIM_],  g_xl [M_*DIM_];
__device__ __nv_bfloat16 g_wqh[NQ_*DIM_], g_wql[NQ_*DIM_];
__device__ __nv_bfloat16 g_wah[NKV_*DIM_],g_wal[NKV_*DIM_];
__device__ __nv_bfloat16 g_wbh[NUP_*RANK_],g_wbl[NUP_*RANK_];
__device__ __nv_bfloat16 g_woh[DIM_*NO_], g_wol[DIM_*NO_];
__device__ __nv_bfloat16 g_kvnh[M_*RANK_],g_kvnl[M_*RANK_];
__device__ __nv_bfloat16 g_ath[M_*NO_],   g_atl[M_*NO_];
__device__ float g_kv  [M_*NKV_];
// head-major bf16 hi/lo operands for attention
__device__ __nv_bfloat16 g_qh[B_*NH_*S_*DQK_], g_ql[B_*NH_*S_*DQK_];
__device__ __nv_bfloat16 g_kh[B_*NH_*S_*DQK_], g_kl[B_*NH_*S_*DQK_];
__device__ __nv_bfloat16 g_vh[B_*NH_*S_*DV_],  g_vl[B_*NH_*S_*DV_];

// ---------------- PTX helpers ----------------
__device__ __forceinline__ uint32_t smem_u32(const void* p){
    uint32_t a;
    asm("{ .reg .u64 t; cvta.to.shared.u64 t, %1; cvt.u32.u64 %0, t; }"
        : "=r"(a) : "l"(p));
    return a;
}
__device__ __forceinline__ void cpa16(uint32_t dst, const void* src, int sz){
    asm volatile("cp.async.cg.shared.global [%0], [%1], 16, %2;"
                 :: "r"(dst), "l"(src), "r"(sz) : "memory");
}
#define CP_COMMIT() asm volatile("cp.async.commit_group;" ::: "memory")
#define CP_WAIT2()  asm volatile("cp.async.wait_group 2;" ::: "memory")
#define CP_WAIT0()  asm volatile("cp.async.wait_group 0;" ::: "memory")

__device__ __forceinline__ void ldsm4(uint32_t* r, uint32_t addr){
    asm volatile("ldmatrix.sync.aligned.m8n8.x4.shared.b16 {%0,%1,%2,%3}, [%4];"
        : "=r"(r[0]), "=r"(r[1]), "=r"(r[2]), "=r"(r[3]) : "r"(addr));
}
__device__ __forceinline__ void ldsm4t(uint32_t* r, uint32_t addr){
    asm volatile("ldmatrix.sync.aligned.m8n8.x4.trans.shared.b16 {%0,%1,%2,%3}, [%4];"
        : "=r"(r[0]), "=r"(r[1]), "=r"(r[2]), "=r"(r[3]) : "r"(addr));
}
__device__ __forceinline__ void mma16816(float* c, const uint32_t* a,
                                         uint32_t b0, uint32_t b1){
    asm volatile("mma.sync.aligned.m16n8k16.row.col.f32.bf16.bf16.f32 "
        "{%0,%1,%2,%3}, {%4,%5,%6,%7}, {%8,%9}, {%0,%1,%2,%3};"
        : "+f"(c[0]), "+f"(c[1]), "+f"(c[2]), "+f"(c[3])
        : "r"(a[0]), "r"(a[1]), "r"(a[2]), "r"(a[3]), "r"(b0), "r"(b1));
}
__device__ __forceinline__ float ex2f(float x){
    float y; asm("ex2.approx.ftz.f32 %0, %1;" : "=f"(y) : "f"(x)); return y;
}

// ---------------- hi/lo bf16 split ----------------
__device__ __forceinline__ void split_bf16(float v, __nv_bfloat16& h, __nv_bfloat16& l){
    h = __float2bfloat16(v);
    l = __float2bfloat16(v - __bfloat162float(h));
}
__device__ __forceinline__ void pksplit(float a, float b, uint32_t& hi, uint32_t& lo){
    __nv_bfloat16 ah, al, bh, bl;
    split_bf16(a, ah, al); split_bf16(b, bh, bl);
    __nv_bfloat162 H; H.x = ah; H.y = bh; hi = *(uint32_t*)&H;
    __nv_bfloat162 L; L.x = al; L.y = bl; lo = *(uint32_t*)&L;
}

__global__ void __launch_bounds__(256) k_cvt(const float* __restrict__ s,
                                             __nv_bfloat16* __restrict__ h,
                                             __nv_bfloat16* __restrict__ l, int n)
{
    int i = (blockIdx.x * 256 + threadIdx.x) * 4;
    if (i >= n) return;
    float4 v = *(const float4*)(s + i);
    __nv_bfloat16 h0, l0, h1, l1, h2, l2, h3, l3;
    split_bf16(v.x, h0, l0); split_bf16(v.y, h1, l1);
    split_bf16(v.z, h2, l2); split_bf16(v.w, h3, l3);
    __nv_bfloat162 p;
    p.x = h0; p.y = h1; *(__nv_bfloat162*)(h + i)     = p;
    p.x = h2; p.y = h3; *(__nv_bfloat162*)(h + i + 2) = p;
    p.x = l0; p.y = l1; *(__nv_bfloat162*)(l + i)     = p;
    p.x = l2; p.y = l3; *(__nv_bfloat162*)(l + i + 2) = p;
}

// ---------------- shared GEMM mainloop (R6 proven config) ------------------
#define STG_BYTES 32768
#define GEMM_SMEM (3*STG_BYTES)

__device__ __forceinline__ void stage_load(uint32_t sdst,
    const char* ah, const char* al, const char* bh, const char* bl,
    int K2, int k0b, int nrem)
{
    const int tid = threadIdx.x;
#pragma unroll
    for (int p = 0; p < 2; p++){
        int idx = tid + p*256;
        int r = idx >> 2, c = idx & 3;
        uint32_t soff = (uint32_t)(r*64 + ((c ^ (r & 3)) << 4));
        size_t go = (size_t)r * K2 + k0b + c*16;
        cpa16(sdst + soff,        ah + go, 16);
        cpa16(sdst + 8192 + soff, al + go, 16);
        int rb = (r < nrem) ? r : 0;
        int sz = (r < nrem) ? 16 : 0;
        size_t gob = (size_t)rb * K2 + k0b + c*16;
        cpa16(sdst + 16384 + soff, bh + gob, sz);
        cpa16(sdst + 24576 + soff, bl + gob, sz);
    }
}

__device__ __forceinline__ void gemm_mainloop(
    const __nv_bfloat16* __restrict__ Ah, const __nv_bfloat16* __restrict__ Al,
    const __nv_bfloat16* __restrict__ Bh, const __nv_bfloat16* __restrict__ Bl,
    int N, int K, float acc[2][8][4], char* smc)
{
    const int tid = threadIdx.x, wid = tid >> 5, lane = tid & 31;
    const int m0 = blockIdx.y * 128, n0 = blockIdx.x * 128;
    const int wm = (wid & 3) * 32, wn = (wid >> 2) * 64;
    const int nrem = N - n0;
    const int K2 = K * 2;
    const int nk = K / 32;

    uint32_t sbase = smem_u32(smc);
    const char* gAh = (const char*)(Ah + (size_t)m0 * K);
    const char* gAl = (const char*)(Al + (size_t)m0 * K);
    const char* gBh = (const char*)(Bh + (size_t)n0 * K);
    const char* gBl = (const char*)(Bl + (size_t)n0 * K);

#pragma unroll
    for (int s = 0; s < 2; s++){
        stage_load(sbase + s*STG_BYTES, gAh, gAl, gBh, gBl, K2, s*64, nrem);
        CP_COMMIT();
    }

#pragma unroll
    for (int a = 0; a < 2; a++)
#pragma unroll
        for (int b = 0; b < 8; b++)
#pragma unroll
            for (int c = 0; c < 4; c++) acc[a][b][c] = 0.f;

    int sidx = 0;
    for (int kt = 0; kt < nk; kt++){
        int ns = kt + 2;
        if (ns < nk){
            int fs = ns - 3*(ns/3);
            stage_load(sbase + fs*STG_BYTES, gAh, gAl, gBh, gBl, K2, ns*64, nrem);
        }
        CP_COMMIT();
        CP_WAIT2();
        __syncthreads();

        uint32_t sb = sbase + sidx*STG_BYTES;
#pragma unroll
        for (int ks = 0; ks < 2; ks++){
            uint32_t afr[2][2][4];
#pragma unroll
            for (int v = 0; v < 2; v++)
#pragma unroll
                for (int mt = 0; mt < 2; mt++){
                    int row = wm + mt*16 + (lane & 15);
                    int ch  = ((ks*2 + (lane >> 4)) ^ (row & 3)) & 3;
                    ldsm4(afr[v][mt], sb + v*8192 + row*64 + ch*16);
                }
#pragma unroll
            for (int np = 0; np < 4; np++){
                uint32_t bh4[4], bl4[4];
                int row = wn + np*16 + ((lane >> 4) << 3) + (lane & 7);
                int ch  = ((ks*2 + ((lane >> 3) & 1)) ^ (row & 3)) & 3;
                ldsm4(bh4, sb + 16384 + row*64 + ch*16);
                ldsm4(bl4, sb + 24576 + row*64 + ch*16);
#pragma unroll
                for (int mt = 0; mt < 2; mt++){
                    mma16816(acc[mt][np*2],   afr[0][mt], bh4[0], bh4[1]);
                    mma16816(acc[mt][np*2+1], afr[0][mt], bh4[2], bh4[3]);
                }
#pragma unroll
                for (int mt = 0; mt < 2; mt++){
                    mma16816(acc[mt][np*2],   afr[0][mt], bl4[0], bl4[1]);
                    mma16816(acc[mt][np*2+1], afr[0][mt], bl4[2], bl4[3]);
                }
#pragma unroll
                for (int mt = 0; mt < 2; mt++){
                    mma16816(acc[mt][np*2],   afr[1][mt], bh4[0], bh4[1]);
                    mma16816(acc[mt][np*2+1], afr[1][mt], bh4[2], bh4[3]);
                }
            }
        }
        __syncthreads();
        sidx = (sidx + 1 == 3) ? 0 : sidx + 1;
    }
}

// ---- generic GEMM: fp32 C output (used for gemm_kv and gemm_o) ----
__global__ void __launch_bounds__(256, 2)
k_mmagemm(const __nv_bfloat16* __restrict__ Ah, const __nv_bfloat16* __restrict__ Al,
          const __nv_bfloat16* __restrict__ Bh, const __nv_bfloat16* __restrict__ Bl,
          float* __restrict__ C, int M, int N, int K)
{
    extern __shared__ char smc[];
    float acc[2][8][4];
    gemm_mainloop(Ah, Al, Bh, Bl, N, K, acc, smc);

    const int tid = threadIdx.x, wid = tid >> 5, lane = tid & 31;
    const int m0 = blockIdx.y * 128, n0 = blockIdx.x * 128;
    const int wm = (wid & 3) * 32, wn = (wid >> 2) * 64;
#pragma unroll
    for (int mt = 0; mt < 2; mt++){
        int row = m0 + wm + mt*16 + (lane >> 2);
#pragma unroll
        for (int nt = 0; nt < 8; nt++){
            int col = n0 + wn + nt*8 + (lane & 3)*2;
            if (col < N){
                float* c = acc[mt][nt];
                *(float2*)(C + (size_t)row*N + col)     = make_float2(c[0], c[1]);
                *(float2*)(C + (size_t)(row+8)*N + col) = make_float2(c[2], c[3]);
            }
        }
    }
}

// ---- gemm_q fused: RoPE + QSCALE + hi/lo split + head-major store ----
__global__ void __launch_bounds__(256, 2)
k_gemmq(const __nv_bfloat16* __restrict__ Ah, const __nv_bfloat16* __restrict__ Al,
        const __nv_bfloat16* __restrict__ Bh, const __nv_bfloat16* __restrict__ Bl,
        const float* __restrict__ fc, int batch)
{
    extern __shared__ char smc[];
    float acc[2][8][4];
    gemm_mainloop(Ah, Al, Bh, Bl, NQ_, DIM_, acc, smc);

    const int tid = threadIdx.x, wid = tid >> 5, lane = tid & 31;
    const int m0 = blockIdx.y * 128, n0 = blockIdx.x * 128;
    const int wm = (wid & 3) * 32, wn = (wid >> 2) * 64;
#pragma unroll
    for (int mt = 0; mt < 2; mt++){
        int r0 = m0 + wm + mt*16 + (lane >> 2);   // seq pos within batch
        int r1 = r0 + 8;
#pragma unroll
        for (int nt = 0; nt < 8; nt++){
            int col = n0 + wn + nt*8 + (lane & 3)*2;
            int hh = col / 192, d = col - hh*192;
            float* c = acc[mt][nt];
            float y0 = c[0], y1 = c[1], z0 = c[2], z1 = c[3];
            if (d >= 128){
                int i = (d - 128) >> 1;
                float cs0 = fc[(size_t)r0*64 + 2*i], sn0 = fc[(size_t)r0*64 + 2*i + 1];
                float cs1 = fc[(size_t)r1*64 + 2*i], sn1 = fc[(size_t)r1*64 + 2*i + 1];
                y0 = c[0]*cs0 - c[1]*sn0; y1 = c[0]*sn0 + c[1]*cs0;
                z0 = c[2]*cs1 - c[3]*sn1; z1 = c[2]*sn1 + c[3]*cs1;
            }
            uint32_t hi, lo;
            size_t o0 = ((size_t)(batch*16 + hh) * S_ + r0) * 192 + d;
            pksplit(y0 * QSCALE, y1 * QSCALE, hi, lo);
            *(uint32_t*)(g_qh + o0) = hi; *(uint32_t*)(g_ql + o0) = lo;
            size_t o1 = ((size_t)(batch*16 + hh) * S_ + r1) * 192 + d;
            pksplit(z0 * QSCALE, z1 * QSCALE, hi, lo);
            *(uint32_t*)(g_qh + o1) = hi; *(uint32_t*)(g_ql + o1) = lo;
        }
    }
}

// ---- kvup fused: route K-nope / V, hi/lo split, head-major store ----
__global__ void __launch_bounds__(256, 2)
k_gemmup(const __nv_bfloat16* __restrict__ Ah, const __nv_bfloat16* __restrict__ Al,
         const __nv_bfloat16* __restrict__ Bh, const __nv_bfloat16* __restrict__ Bl)
{
    extern __shared__ char smc[];
    float acc[2][8][4];
    gemm_mainloop(Ah, Al, Bh, Bl, NUP_, RANK_, acc, smc);

    const int tid = threadIdx.x, wid = tid >> 5, lane = tid & 31;
    const int m0 = blockIdx.y * 128, n0 = blockIdx.x * 128;
    const int wm = (wid & 3) * 32, wn = (wid >> 2) * 64;
#pragma unroll
    for (int mt = 0; mt < 2; mt++){
        int m = m0 + wm + mt*16 + (lane >> 2);   // global row (b*S + s)
        int b = m >> 11, s = m & (S_ - 1);       // rows m, m+8 same batch (16-aligned blocks)
#pragma unroll
        for (int nt = 0; nt < 8; nt++){
            int col = n0 + wn + nt*8 + (lane & 3)*2;
            int hh = col >> 8, dd = col & 255;
            float* c = acc[mt][nt];
            uint32_t hi, lo;
            if (dd < 128){   // K-nope
                size_t o0 = ((size_t)(b*16 + hh) * S_ + s) * 192 + dd;
                pksplit(c[0], c[1], hi, lo);
                *(uint32_t*)(g_kh + o0) = hi; *(uint32_t*)(g_kl + o0) = lo;
                size_t o1 = ((size_t)(b*16 + hh) * S_ + s + 8) * 192 + dd;
                pksplit(c[2], c[3], hi, lo);
                *(uint32_t*)(g_kh + o1) = hi; *(uint32_t*)(g_kl + o1) = lo;
            } else {          // V
                int d = dd - 128;
                size_t o0 = ((size_t)(b*16 + hh) * S_ + s) * 128 + d;
                pksplit(c[0], c[1], hi, lo);
                *(uint32_t*)(g_vh + o0) = hi; *(uint32_t*)(g_vl + o0) = lo;
                size_t o1 = ((size_t)(b*16 + hh) * S_ + s + 8) * 128 + d;
                pksplit(c[2], c[3], hi, lo);
                *(uint32_t*)(g_vh + o1) = hi; *(uint32_t*)(g_vl + o1) = lo;
            }
        }
    }
}

// ---------------- ew: rmsnorm + k_pe RoPE broadcast into g_kh/g_kl ----------
__global__ void __launch_bounds__(256) k_ew(const float* __restrict__ fc,
                                            const float* __restrict__ knw)
{
    __shared__ float red[8];
    __shared__ float rsv;
    __shared__ float kp[64];
    const int m   = blockIdx.x;
    const int b   = m >> 11;
    const int s   = m & (S_ - 1);
    const int tid = threadIdx.x;
    const float* kvrow = g_kv + (size_t)m * NKV_;

    float v0 = kvrow[tid];
    float v1 = kvrow[tid + 256];
    float ss = v0 * v0 + v1 * v1;
#pragma unroll
    for (int o = 16; o; o >>= 1) ss += __shfl_xor_sync(0xffffffffu, ss, o);
    if ((tid & 31) == 0) red[tid >> 5] = ss;
    __syncthreads();
    if (tid == 0) {
        float tt = 0.f;
#pragma unroll
        for (int i = 0; i < 8; i++) tt += red[i];
        rsv = rsqrtf(tt / (float)RANK_ + 1e-6f);
    }
    if (tid < 32) {
        float c  = fc[(size_t)s * 64 + 2 * tid];
        float sn = fc[(size_t)s * 64 + 2 * tid + 1];
        float x0 = kvrow[RANK_ + 2 * tid];
        float x1 = kvrow[RANK_ + 2 * tid + 1];
        kp[2*tid]     = x0 * c - x1 * sn;
        kp[2*tid + 1] = x0 * sn + x1 * c;
    }
    __syncthreads();
    const float rs = rsv;
    {
        float y0 = v0 * rs * knw[tid];
        float y1 = v1 * rs * knw[tid + 256];
        size_t o0 = (size_t)m * RANK_ + tid;
        __nv_bfloat16 h, l;
        split_bf16(y0, h, l); g_kvnh[o0]       = h; g_kvnl[o0]       = l;
        split_bf16(y1, h, l); g_kvnh[o0 + 256] = h; g_kvnl[o0 + 256] = l;
    }
    // broadcast k_pe into all 16 heads' K region [128:192)
#pragma unroll
    for (int idx = tid; idx < 512; idx += 256){
        int hh = idx >> 5, pr = idx & 31;
        int d = 2*pr;
        uint32_t hi, lo;
        pksplit(kp[d], kp[d+1], hi, lo);
        size_t o = ((size_t)(b*16 + hh) * S_ + s) * 192 + 128 + d;
        *(uint32_t*)(g_kh + o) = hi;
        *(uint32_t*)(g_kl + o) = lo;
    }
}

// ---------------- HMMA flash attention v4 (per batch): 2 CTAs/SM ------------
#define A4_KH 0
#define A4_KL 24576
#define A4_VH 49152
#define A4_VL 65536
#define A4_QL 81920
#define ATT4_SMEM 106496

__device__ __forceinline__ uint32_t swzK(int r, int c){
    return (uint32_t)(r*384 + (((c & ~7) | ((c & 7) ^ (r & 7))) << 4));
}
__device__ __forceinline__ uint32_t swzV(int r, int c){
    return (uint32_t)(r*256 + (((c & 8) | ((c & 7) ^ (r & 7))) << 4));
}

__global__ void __launch_bounds__(128, 2) k_attn4(int batch)
{
    extern __shared__ char sm[];
    uint32_t sb = smem_u32(sm);
    const int tid = threadIdx.x, wid = tid >> 5, lane = tid & 31;
    const int h  = blockIdx.y;
    const int b  = batch;
    const int bh = b*16 + h;
    const int qi = gridDim.x - 1 - blockIdx.x;
    const int qb = qi * 64;
    const int nt = qi + 1;

    const __nv_bfloat16* gqh = g_qh + ((size_t)bh * S_ + qb) * 192;
    const __nv_bfloat16* gql = g_ql + ((size_t)bh * S_ + qb) * 192;
    const __nv_bfloat16* gkh = g_kh + (size_t)bh * S_ * 192;
    const __nv_bfloat16* gkl = g_kl + (size_t)bh * S_ * 192;
    const __nv_bfloat16* gvh = g_vh + (size_t)bh * S_ * 128;
    const __nv_bfloat16* gvl = g_vl + (size_t)bh * S_ * 128;

#pragma unroll
    for (int p = 0; p < 12; p++){
        int i = tid + p*128;
        int r = i / 24, c = i - r*24;
        uint32_t so = swzK(r, c);
        cpa16(sb + A4_KH + so, (const char*)gqh + (size_t)r*384 + c*16, 16);
        cpa16(sb + A4_QL + so, (const char*)gql + (size_t)r*384 + c*16, 16);
    }
    CP_COMMIT(); CP_WAIT0();
    __syncthreads();

    uint32_t qh[12][4];
    {
        int row = wid*16 + (lane & 15);
#pragma unroll
        for (int kc = 0; kc < 12; kc++){
            int c = 2*kc + (lane >> 4);
            ldsm4(qh[kc], sb + A4_KH + swzK(row, c));
        }
    }

    float oacc[16][4];
#pragma unroll
    for (int n = 0; n < 16; n++)
#pragma unroll
        for (int c = 0; c < 4; c++) oacc[n][c] = 0.f;
    float m0 = -CUDART_INF_F, m1 = -CUDART_INF_F, l0 = 0.f, l1 = 0.f;

    const int qr0 = qb + wid*16 + (lane >> 2);
    const int koff = 2*(lane & 3);
    const int qrow = wid*16 + (lane & 15);

    for (int t = 0; t < nt; t++){
        __syncthreads();
        {
            const int kb0 = t*64;
#pragma unroll
            for (int p = 0; p < 12; p++){
                int i = tid + p*128;
                int r = i / 24, c = i - r*24;
                uint32_t so = swzK(r, c);
                cpa16(sb + A4_KH + so, (const char*)(gkh + (size_t)(kb0 + r)*192) + c*16, 16);
                cpa16(sb + A4_KL + so, (const char*)(gkl + (size_t)(kb0 + r)*192) + c*16, 16);
            }
#pragma unroll
            for (int p = 0; p < 8; p++){
                int i = tid + p*128;
                int r = i >> 4, c = i & 15;
                uint32_t so = swzV(r, c);
                cpa16(sb + A4_VH + so, (const char*)(gvh + (size_t)(kb0 + r)*128) + c*16, 16);
                cpa16(sb + A4_VL + so, (const char*)(gvl + (size_t)(kb0 + r)*128) + c*16, 16);
            }
        }
        CP_COMMIT(); CP_WAIT0();
        __syncthreads();

        float sacc[8][4];
#pragma unroll
        for (int j = 0; j < 8; j++)
#pragma unroll
            for (int c = 0; c < 4; c++) sacc[j][c] = 0.f;

#pragma unroll
        for (int kc = 0; kc < 12; kc++){
            uint32_t qlf[4];
            {
                int c = 2*kc + (lane >> 4);
                ldsm4(qlf, sb + A4_QL + swzK(qrow, c));
            }
#pragma unroll
            for (int g = 0; g < 4; g++){
                int rowb = g*16 + ((lane >> 4) << 3) + (lane & 7);
                int c = 2*kc + ((lane >> 3) & 1);
                uint32_t so = swzK(rowb, c);
                uint32_t kh4[4], kl4[4];
                ldsm4(kh4, sb + A4_KH + so);
                ldsm4(kl4, sb + A4_KL + so);
                mma16816(sacc[2*g],   qh[kc], kh4[0], kh4[1]);
                mma16816(sacc[2*g+1], qh[kc], kh4[2], kh4[3]);
                mma16816(sacc[2*g],   qlf,    kh4[0], kh4[1]);
                mma16816(sacc[2*g+1], qlf,    kh4[2], kh4[3]);
                mma16816(sacc[2*g],   qh[kc], kl4[0], kl4[1]);
                mma16816(sacc[2*g+1], qh[kc], kl4[2], kl4[3]);
            }
        }

        const int kb = t*64;
        if (kb + 63 > qr0){
#pragma unroll
            for (int j = 0; j < 8; j++){
                if (kb + koff + 8*j     > qr0) sacc[j][0] = -CUDART_INF_F;
                if (kb + koff + 8*j + 1 > qr0) sacc[j][1] = -CUDART_INF_F;
            }
        }
        if (kb + 63 > qr0 + 8){
#pragma unroll
            for (int j = 0; j < 8; j++){
                if (kb + koff + 8*j     > qr0 + 8) sacc[j][2] = -CUDART_INF_F;
                if (kb + koff + 8*j + 1 > qr0 + 8) sacc[j][3] = -CUDART_INF_F;
            }
        }

        float mt0 = -CUDART_INF_F, mt1 = -CUDART_INF_F;
#pragma unroll
        for (int j = 0; j < 8; j++){
            mt0 = fmaxf(mt0, fmaxf(sacc[j][0], sacc[j][1]));
            mt1 = fmaxf(mt1, fmaxf(sacc[j][2], sacc[j][3]));
        }
        mt0 = fmaxf(mt0, __shfl_xor_sync(0xffffffffu, mt0, 1));
        mt0 = fmaxf(mt0, __shfl_xor_sync(0xffffffffu, mt0, 2));
        mt1 = fmaxf(mt1, __shfl_xor_sync(0xffffffffu, mt1, 1));
        mt1 = fmaxf(mt1, __shfl_xor_sync(0xffffffffu, mt1, 2));
        float nm0 = fmaxf(m0, mt0), nm1 = fmaxf(m1, mt1);
        float f0 = ex2f(m0 - nm0);
        float f1 = ex2f(m1 - nm1);
        float ps0 = 0.f, ps1 = 0.f;
#pragma unroll
        for (int j = 0; j < 8; j++){
            sacc[j][0] = ex2f(sacc[j][0] - nm0); ps0 += sacc[j][0];
            sacc[j][1] = ex2f(sacc[j][1] - nm0); ps0 += sacc[j][1];
            sacc[j][2] = ex2f(sacc[j][2] - nm1); ps1 += sacc[j][2];
            sacc[j][3] = ex2f(sacc[j][3] - nm1); ps1 += sacc[j][3];
        }
        ps0 += __shfl_xor_sync(0xffffffffu, ps0, 1);
        ps0 += __shfl_xor_sync(0xffffffffu, ps0, 2);
        ps1 += __shfl_xor_sync(0xffffffffu, ps1, 1);
        ps1 += __shfl_xor_sync(0xffffffffu, ps1, 2);
        l0 = l0*f0 + ps0; l1 = l1*f1 + ps1;
        m0 = nm0; m1 = nm1;

#pragma unroll
        for (int n = 0; n < 16; n++){
            oacc[n][0] *= f0; oacc[n][1] *= f0;
            oacc[n][2] *= f1; oacc[n][3] *= f1;
        }

        uint32_t ph[4][4], pl[4][4];
#pragma unroll
        for (int tt = 0; tt < 4; tt++){
            pksplit(sacc[2*tt][0],   sacc[2*tt][1],   ph[tt][0], pl[tt][0]);
            pksplit(sacc[2*tt][2],   sacc[2*tt][3],   ph[tt][1], pl[tt][1]);
            pksplit(sacc[2*tt+1][0], sacc[2*tt+1][1], ph[tt][2], pl[tt][2]);
            pksplit(sacc[2*tt+1][2], sacc[2*tt+1][3], ph[tt][3], pl[tt][3]);
        }

#pragma unroll
        for (int tt = 0; tt < 4; tt++){
            int rowv = tt*16 + ((lane & 7) | (((lane >> 3) & 1) << 3));
#pragma unroll
            for (int g = 0; g < 8; g++){
                int c = 2*g + (lane >> 4);
                uint32_t so = swzV(rowv, c);
                uint32_t vh4[4], vl4[4];
                ldsm4t(vh4, sb + A4_VH + so);
                ldsm4t(vl4, sb + A4_VL + so);
                mma16816(oacc[2*g],   ph[tt], vh4[0], vh4[1]);
                mma16816(oacc[2*g+1], ph[tt], vh4[2], vh4[3]);
                mma16816(oacc[2*g],   pl[tt], vh4[0], vh4[1]);
                mma16816(oacc[2*g+1], pl[tt], vh4[2], vh4[3]);
                mma16816(oacc[2*g],   ph[tt], vl4[0], vl4[1]);
                mma16816(oacc[2*g+1], ph[tt], vl4[2], vl4[3]);
            }
        }
    }

    float il0 = 1.0f / l0, il1 = 1.0f / l1;
    const int r0 = qb + wid*16 + (lane >> 2);
    size_t ro0 = (size_t)(b*S_ + r0) * NO_ + h*128;
    size_t ro1 = (size_t)(b*S_ + r0 + 8) * NO_ + h*128;
#pragma unroll
    for (int n = 0; n < 16; n++){
        int col = n*8 + 2*(lane & 3);
        uint32_t hi, lo;
        pksplit(oacc[n][0]*il0, oacc[n][1]*il0, hi, lo);
        *(uint32_t*)(g_ath + ro0 + col) = hi;
        *(uint32_t*)(g_atl + ro0 + col) = lo;
        pksplit(oacc[n][2]*il1, oacc[n][3]*il1, hi, lo);
        *(uint32_t*)(g_ath + ro1 + col) = hi;
        *(uint32_t*)(g_atl + ro1 + col) = lo;
    }
}

// ---------------- launch ----------------
static void* sym_addr(const void* s) { void* p = nullptr; cudaGetSymbolAddress(&p, s); return p; }

extern "C" void kernel_launch(void* const* d_in, const int* in_sizes, int n_in,
                              void* d_out, int out_size)
{
    const float* x   = (const float*)d_in[0];
    const float* fc  = (const float*)d_in[2];
    const float* wq  = (const float*)d_in[4];
    const float* wa  = (const float*)d_in[5];
    const float* wb  = (const float*)d_in[6];
    const float* wo  = (const float*)d_in[7];
    const float* knw = (const float*)d_in[8];
    float* out = (float*)d_out;

    cudaFuncSetAttribute(k_mmagemm, cudaFuncAttributeMaxDynamicSharedMemorySize, GEMM_SMEM);
    cudaFuncSetAttribute(k_gemmq,   cudaFuncAttributeMaxDynamicSharedMemorySize, GEMM_SMEM);
    cudaFuncSetAttribute(k_gemmup,  cudaFuncAttributeMaxDynamicSharedMemorySize, GEMM_SMEM);
    cudaFuncSetAttribute(k_attn4,   cudaFuncAttributeMaxDynamicSharedMemorySize, ATT4_SMEM);

    static cudaStream_t s1 = nullptr, s2 = nullptr;
    static cudaEvent_t evFork, evQ0, evKV, evWO, evE1, evE2;
    if (!s1){
        cudaStreamCreateWithFlags(&s1, cudaStreamNonBlocking);
        cudaStreamCreateWithFlags(&s2, cudaStreamNonBlocking);
        cudaEventCreateWithFlags(&evFork, cudaEventDisableTiming);
        cudaEventCreateWithFlags(&evQ0,   cudaEventDisableTiming);
        cudaEventCreateWithFlags(&evKV,   cudaEventDisableTiming);
        cudaEventCreateWithFlags(&evWO,   cudaEventDisableTiming);
        cudaEventCreateWithFlags(&evE1,   cudaEventDisableTiming);
        cudaEventCreateWithFlags(&evE2,   cudaEventDisableTiming);
    }

    __nv_bfloat16 *xh  = (__nv_bfloat16*)sym_addr(g_xh),  *xl  = (__nv_bfloat16*)sym_addr(g_xl);
    __nv_bfloat16 *wqh = (__nv_bfloat16*)sym_addr(g_wqh), *wql = (__nv_bfloat16*)sym_addr(g_wql);
    __nv_bfloat16 *wah = (__nv_bfloat16*)sym_addr(g_wah), *wal = (__nv_bfloat16*)sym_addr(g_wal);
    __nv_bfloat16 *wbh = (__nv_bfloat16*)sym_addr(g_wbh), *wbl = (__nv_bfloat16*)sym_addr(g_wbl);
    __nv_bfloat16 *woh = (__nv_bfloat16*)sym_addr(g_woh), *wol = (__nv_bfloat16*)sym_addr(g_wol);
    __nv_bfloat16 *kvh = (__nv_bfloat16*)sym_addr(g_kvnh),*kvl = (__nv_bfloat16*)sym_addr(g_kvnl);
    __nv_bfloat16 *ath = (__nv_bfloat16*)sym_addr(g_ath), *atl = (__nv_bfloat16*)sym_addr(g_atl);
    float *kvf = (float*)sym_addr(g_kv);

    const size_t XB  = (size_t)S_ * DIM_;
    const size_t AOB = (size_t)S_ * NO_;

    dim3 t(256);

    // --- s0: x + wa conversions, then fork
    k_cvt<<<(M_*DIM_)/1024,   t>>>(x,  xh,  xl,  M_*DIM_);
    k_cvt<<<(NKV_*DIM_)/1024, t>>>(wa, wah, wal, NKV_*DIM_);
    cudaEventRecord(evFork, 0);
    cudaStreamWaitEvent(s1, evFork, 0);

    // --- s1: wq cvt -> gemm_q b0 (fused, evQ0) -> gemm_q b1 (fused)
    k_cvt<<<(NQ_*DIM_)/1024, t, 0, s1>>>(wq, wqh, wql, NQ_*DIM_);
    k_gemmq<<<dim3(NQ_/128, S_/128), t, GEMM_SMEM, s1>>>(xh, xl, wqh, wql, fc, 0);
    cudaEventRecord(evQ0, s1);
    k_gemmq<<<dim3(NQ_/128, S_/128), t, GEMM_SMEM, s1>>>(xh + XB, xl + XB, wqh, wql, fc, 1);

    // --- s0: kv chain (concurrent with gemm_q): gemm_kv -> ew -> kvup(fused)
    k_mmagemm<<<dim3((NKV_+127)/128, M_/128), t, GEMM_SMEM>>>(xh, xl, wah, wal, kvf, M_, NKV_, DIM_);
    k_ew<<<M_, 256>>>(fc, knw);
    k_cvt<<<(NUP_*RANK_)/1024, t>>>(wb, wbh, wbl, NUP_*RANK_);
    k_gemmup<<<dim3(NUP_/128, M_/128), t, GEMM_SMEM>>>(kvh, kvl, wbh, wbl);
    cudaEventRecord(evKV, 0);
    k_cvt<<<(DIM_*NO_)/1024, t>>>(wo, woh, wol, DIM_*NO_);
    cudaEventRecord(evWO, 0);

    // --- s2: b0 tail (attn directly; no qkvcvt)
    cudaStreamWaitEvent(s2, evQ0, 0);
    cudaStreamWaitEvent(s2, evKV, 0);
    k_attn4<<<dim3(S_/64, NH_), dim3(128), ATT4_SMEM, s2>>>(0);
    cudaStreamWaitEvent(s2, evWO, 0);
    k_mmagemm<<<dim3(DIM_/128, S_/128), t, GEMM_SMEM, s2>>>(ath, atl, woh, wol, out, S_, DIM_, NO_);
    cudaEventRecord(evE2, s2);

    // --- s1: b1 tail
    cudaStreamWaitEvent(s1, evKV, 0);
    k_attn4<<<dim3(S_/64, NH_), dim3(128), ATT4_SMEM, s1>>>(1);
    cudaStreamWaitEvent(s1, evWO, 0);
    k_mmagemm<<<dim3(DIM_/128, S_/128), t, GEMM_SMEM, s1>>>(
        ath + AOB, atl + AOB, woh, wol, out + (size_t)S_*DIM_, S_, DIM_, NO_);
    cudaEventRecord(evE1, s1);

    // --- join
    cudaStreamWaitEvent(0, evE1, 0);
    cudaStreamWaitEvent(0, evE2, 0);
}